// round 9
// baseline (speedup 1.0000x reference)
#include <cuda_runtime.h>
#include <math.h>
#include <stdint.h>

#define NB 32
#define NL 128
#define NH 512
#define NG 2048
#define NV 32000
#define NE 128
#define NTOK 4096
#define NVT 250

// weight-plane arena offsets (floats)
#define OFF_WIH0 0
#define OFF_WIH1 524288
#define OFF_W1   8912896
#define OFF_W2   9043968
#define WARENA   13139968

// ------------------ scratch ------------------
__device__ float g_wh[WARENA];
__device__ float g_wl[WARENA];
__device__ float g_whhh[3 * 2 * NG * NH];
__device__ float g_whhl[3 * 2 * NG * NH];
__device__ float g_ah[NTOK * 1024];
__device__ float g_al[NTOK * 1024];
__device__ float g_gx[2u * NTOK * NG];          // [dir][m][g], m = b*128+t
__device__ float g_bufA[NTOK * 1024];
__device__ float g_bufB[NTOK * 1024];
__device__ float g_hid[NTOK * 128];
__device__ float g_hidh[NTOK * 128];
__device__ float g_hidl[NTOK * 128];
__device__ float g_hph[2 * 2 * NB * NH];        // [parity][dir][b][j]
__device__ float g_hpl[2 * 2 * NB * NH];
__device__ float g_pmax[(size_t)NTOK * NVT];
__device__ float g_psum[(size_t)NTOK * NVT];
__device__ int   g_parg[(size_t)NTOK * NVT];
__device__ float g_nllw[NTOK];
__device__ float g_wtok[NTOK];
__device__ unsigned int g_barcnt;

// ------------------ helpers ------------------
__device__ __forceinline__ float sigf(float x) {
    return 1.0f / (1.0f + __expf(-x));
}
__device__ __forceinline__ float tanhf_fast(float x) {
    float e = __expf(-2.0f * fabsf(x));
    float r = (1.0f - e) / (1.0f + e);
    return copysignf(r, x);
}

__device__ __forceinline__ void gridbar() {
    __syncthreads();
    if (threadIdx.x == 0) {
        unsigned int t = atomicAdd(&g_barcnt, 1u);
        unsigned int need = ((t >> 7) + 1u) << 7;
        while (*((volatile unsigned int*)&g_barcnt) < need) {
            __nanosleep(32);
        }
    }
    __syncthreads();
}

__device__ __forceinline__ void tf32split(float x, float& hi, float& lo) {
    unsigned hb;
    asm("cvt.rna.tf32.f32 %0, %1;" : "=r"(hb) : "f"(x));
    float hf = __uint_as_float(hb);
    float l = x - hf;
    unsigned lb;
    asm("cvt.rna.tf32.f32 %0, %1;" : "=r"(lb) : "f"(l));
    hi = hf;
    lo = __uint_as_float(lb);
}

#define MMA_TF32(c, a, b)                                                     \
    asm volatile(                                                             \
        "mma.sync.aligned.m16n8k8.row.col.f32.tf32.tf32.f32 "                 \
        "{%0,%1,%2,%3}, {%4,%5,%6,%7}, {%8,%9}, {%0,%1,%2,%3};"               \
        : "+f"((c)[0]), "+f"((c)[1]), "+f"((c)[2]), "+f"((c)[3])              \
        : "r"((a)[0]), "r"((a)[1]), "r"((a)[2]), "r"((a)[3]),                 \
          "r"((b)[0]), "r"((b)[1]))

__device__ __forceinline__ void cp16(uint32_t dst, const float* src) {
    asm volatile("cp.async.cg.shared.global [%0], [%1], 16;" :: "r"(dst), "l"(src));
}
#define CP_COMMIT() asm volatile("cp.async.commit_group;")
#define CP_WAIT1()  asm volatile("cp.async.wait_group 1;")
#define CP_WAIT0()  asm volatile("cp.async.wait_group 0;")

// gemm stage layout: 4 planes (AH, AL, BH, BL) x 128 rows x 20 floats
#define PLANE 2560
#define STAGE 10240

// scan v5 smem layout (floats)
#define SC_WH 0
#define SC_WL 16512
#define SC_HB 33024
#define SC_GS 49920
#define SC_TOT 50976

// ------------------ split kernel ------------------
__global__ __launch_bounds__(256) void k_split(const float* __restrict__ s,
                                               float* __restrict__ dh,
                                               float* __restrict__ dl, int n4) {
    int i = blockIdx.x * 256 + threadIdx.x;
    if (i < n4) {
        float4 v = ((const float4*)s)[i];
        float4 h4, l4;
        tf32split(v.x, h4.x, l4.x);
        tf32split(v.y, h4.y, l4.y);
        tf32split(v.z, h4.z, l4.z);
        tf32split(v.w, h4.w, l4.w);
        ((float4*)dh)[i] = h4;
        ((float4*)dl)[i] = l4;
    }
}

// ------------------ embedding (writes split planes) ------------------
__global__ __launch_bounds__(256) void k_embed(const int* __restrict__ w,
                                               const float* __restrict__ emb) {
    int i = blockIdx.x * 256 + threadIdx.x;
    float v = emb[(size_t)w[i >> 7] * NE + (i & 127)];
    float h, l;
    tf32split(v, h, l);
    g_ah[i] = h;
    g_al[i] = l;
}

// ------------------ zero h planes (parity 0) + barrier ------------------
__global__ __launch_bounds__(256) void k_zero() {
    int i = blockIdx.x * 256 + threadIdx.x;
    if (i < 2 * NB * NH) { g_hph[i] = 0.0f; g_hpl[i] = 0.0f; }
    if (i == 0) g_barcnt = 0u;
}

// ------------------ 3xTF32 mma GEMM, presplit inputs, cp.async pipeline ----
__global__ __launch_bounds__(256) void k_gemm2(const float* __restrict__ Ahp,
                                               const float* __restrict__ Alp,
                                               const float* __restrict__ Whp,
                                               const float* __restrict__ Wlp,
                                               const float* __restrict__ bias,
                                               float* __restrict__ C,
                                               int K, int N,
                                               long long wStr, long long bStr,
                                               long long cStr, int mode) {
    extern __shared__ float smf[];
    uint32_t smb = (uint32_t)__cvta_generic_to_shared(smf);

    int d = blockIdx.z;
    Whp += (size_t)d * wStr;
    Wlp += (size_t)d * wStr;
    bias += (size_t)d * bStr;
    C += (size_t)d * cStr;

    int tid = threadIdx.x;
    int m0 = blockIdx.y << 7, n0 = blockIdx.x << 7;
    int lr = tid >> 2, lkq = (tid & 3) << 2;

    const float* pA0h = Ahp + (size_t)(m0 + lr) * K + lkq;
    const float* pA1h = Ahp + (size_t)(m0 + lr + 64) * K + lkq;
    const float* pA0l = Alp + (size_t)(m0 + lr) * K + lkq;
    const float* pA1l = Alp + (size_t)(m0 + lr + 64) * K + lkq;
    const float* pB0h = Whp + (size_t)(n0 + lr) * K + lkq;
    const float* pB1h = Whp + (size_t)(n0 + lr + 64) * K + lkq;
    const float* pB0l = Wlp + (size_t)(n0 + lr) * K + lkq;
    const float* pB1l = Wlp + (size_t)(n0 + lr + 64) * K + lkq;

    uint32_t o0 = (uint32_t)((0 * PLANE + lr * 20 + lkq) * 4);
    uint32_t o1 = (uint32_t)((0 * PLANE + (lr + 64) * 20 + lkq) * 4);
    uint32_t o2 = (uint32_t)((1 * PLANE + lr * 20 + lkq) * 4);
    uint32_t o3 = (uint32_t)((1 * PLANE + (lr + 64) * 20 + lkq) * 4);
    uint32_t o4 = (uint32_t)((2 * PLANE + lr * 20 + lkq) * 4);
    uint32_t o5 = (uint32_t)((2 * PLANE + (lr + 64) * 20 + lkq) * 4);
    uint32_t o6 = (uint32_t)((3 * PLANE + lr * 20 + lkq) * 4);
    uint32_t o7 = (uint32_t)((3 * PLANE + (lr + 64) * 20 + lkq) * 4);

    int wid = tid >> 5, lane = tid & 31;
    int gid = lane >> 2, t4 = lane & 3;
    int wm = (wid >> 2) << 6;
    int wn = (wid & 3) << 5;

    float acc[4][4][4];
#pragma unroll
    for (int mt = 0; mt < 4; mt++)
#pragma unroll
        for (int nt = 0; nt < 4; nt++)
#pragma unroll
            for (int r = 0; r < 4; r++) acc[mt][nt][r] = 0.0f;

    int T = K >> 4;
    {
        uint32_t b = smb;
        cp16(b + o0, pA0h); cp16(b + o1, pA1h);
        cp16(b + o2, pA0l); cp16(b + o3, pA1l);
        cp16(b + o4, pB0h); cp16(b + o5, pB1h);
        cp16(b + o6, pB0l); cp16(b + o7, pB1l);
        CP_COMMIT();
    }

    for (int kt = 0; kt < T; kt++) {
        int s = kt & 1;
        if (kt + 1 < T) {
            int ko = (kt + 1) << 4;
            uint32_t b = smb + (uint32_t)((s ^ 1) * STAGE * 4);
            cp16(b + o0, pA0h + ko); cp16(b + o1, pA1h + ko);
            cp16(b + o2, pA0l + ko); cp16(b + o3, pA1l + ko);
            cp16(b + o4, pB0h + ko); cp16(b + o5, pB1h + ko);
            cp16(b + o6, pB0l + ko); cp16(b + o7, pB1l + ko);
            CP_COMMIT();
            CP_WAIT1();
        } else {
            CP_WAIT0();
        }
        __syncthreads();
        const float* S = smf + s * STAGE;

#pragma unroll
        for (int k8 = 0; k8 < 16; k8 += 8) {
            unsigned ah[4][4], al[4][4];
#pragma unroll
            for (int mt = 0; mt < 4; mt++) {
                int r0i = (wm + (mt << 4) + gid) * 20 + k8 + t4;
                int r1i = (wm + (mt << 4) + gid + 8) * 20 + k8 + t4;
                ah[mt][0] = __float_as_uint(S[r0i]);
                ah[mt][1] = __float_as_uint(S[r1i]);
                ah[mt][2] = __float_as_uint(S[r0i + 4]);
                ah[mt][3] = __float_as_uint(S[r1i + 4]);
                al[mt][0] = __float_as_uint(S[PLANE + r0i]);
                al[mt][1] = __float_as_uint(S[PLANE + r1i]);
                al[mt][2] = __float_as_uint(S[PLANE + r0i + 4]);
                al[mt][3] = __float_as_uint(S[PLANE + r1i + 4]);
            }
            unsigned bh[4][2], bl[4][2];
#pragma unroll
            for (int nt = 0; nt < 4; nt++) {
                int ci = (wn + (nt << 3) + gid) * 20 + k8 + t4;
                bh[nt][0] = __float_as_uint(S[2 * PLANE + ci]);
                bh[nt][1] = __float_as_uint(S[2 * PLANE + ci + 4]);
                bl[nt][0] = __float_as_uint(S[3 * PLANE + ci]);
                bl[nt][1] = __float_as_uint(S[3 * PLANE + ci + 4]);
            }
#pragma unroll
            for (int mt = 0; mt < 4; mt++)
#pragma unroll
                for (int nt = 0; nt < 4; nt++) {
                    MMA_TF32(acc[mt][nt], ah[mt], bh[nt]);
                    MMA_TF32(acc[mt][nt], ah[mt], bl[nt]);
                    MMA_TF32(acc[mt][nt], al[mt], bh[nt]);
                }
        }
        __syncthreads();
    }

#pragma unroll
    for (int mt = 0; mt < 4; mt++) {
#pragma unroll
        for (int nt = 0; nt < 4; nt++) {
            int m = m0 + wm + (mt << 4) + gid;
            int n = n0 + wn + (nt << 3) + (t4 << 1);
            float bv0 = bias[n], bv1 = bias[n + 1];
            float v0 = acc[mt][nt][0] + bv0;
            float v1 = acc[mt][nt][1] + bv1;
            float v2 = acc[mt][nt][2] + bv0;
            float v3 = acc[mt][nt][3] + bv1;
            if (mode) {
                v0 = fmaxf(v0, 0.0f); v1 = fmaxf(v1, 0.0f);
                v2 = fmaxf(v2, 0.0f); v3 = fmaxf(v3, 0.0f);
            }
            float2 p0 = {v0, v1};
            float2 p1 = {v2, v3};
            *(float2*)(C + (size_t)m * N + n) = p0;
            *(float2*)(C + (size_t)(m + 8) * N + n) = p1;
            if (mode == 2) {
                float h, l;
                size_t i0 = (size_t)m * N + n;
                size_t i1 = (size_t)(m + 8) * N + n;
                tf32split(v0, h, l); g_hidh[i0] = h;     g_hidl[i0] = l;
                tf32split(v1, h, l); g_hidh[i0 + 1] = h; g_hidl[i0 + 1] = l;
                tf32split(v2, h, l); g_hidh[i1] = h;     g_hidl[i1] = l;
                tf32split(v3, h, l); g_hidh[i1 + 1] = h; g_hidl[i1 + 1] = l;
            }
        }
    }
}

// ------------------ decoder2 mma: logits tile + online softmax partials ----
__global__ __launch_bounds__(256) void k_dec2m(const float* __restrict__ b2) {
    extern __shared__ float smf[];
    uint32_t smb = (uint32_t)__cvta_generic_to_shared(smf);
    __shared__ float wmax[256];
    __shared__ int   warg[256];
    __shared__ float wsum[256];
    __shared__ float bmx[128];

    const float* Ahp = g_wh + OFF_W2;
    const float* Alp = g_wl + OFF_W2;

    int tid = threadIdx.x;
    int vt = blockIdx.x;
    int v0 = vt << 7;
    int n0 = blockIdx.y << 7;
    int lr = tid >> 2, lkq = (tid & 3) << 2;
    const int K = 128;

    const float* pA0h = Ahp + (size_t)(v0 + lr) * K + lkq;
    const float* pA1h = Ahp + (size_t)(v0 + lr + 64) * K + lkq;
    const float* pA0l = Alp + (size_t)(v0 + lr) * K + lkq;
    const float* pA1l = Alp + (size_t)(v0 + lr + 64) * K + lkq;
    const float* pB0h = g_hidh + (size_t)(n0 + lr) * K + lkq;
    const float* pB1h = g_hidh + (size_t)(n0 + lr + 64) * K + lkq;
    const float* pB0l = g_hidl + (size_t)(n0 + lr) * K + lkq;
    const float* pB1l = g_hidl + (size_t)(n0 + lr + 64) * K + lkq;

    uint32_t o0 = (uint32_t)((0 * PLANE + lr * 20 + lkq) * 4);
    uint32_t o1 = (uint32_t)((0 * PLANE + (lr + 64) * 20 + lkq) * 4);
    uint32_t o2 = (uint32_t)((1 * PLANE + lr * 20 + lkq) * 4);
    uint32_t o3 = (uint32_t)((1 * PLANE + (lr + 64) * 20 + lkq) * 4);
    uint32_t o4 = (uint32_t)((2 * PLANE + lr * 20 + lkq) * 4);
    uint32_t o5 = (uint32_t)((2 * PLANE + (lr + 64) * 20 + lkq) * 4);
    uint32_t o6 = (uint32_t)((3 * PLANE + lr * 20 + lkq) * 4);
    uint32_t o7 = (uint32_t)((3 * PLANE + (lr + 64) * 20 + lkq) * 4);

    int wid = tid >> 5, lane = tid & 31;
    int gid = lane >> 2, t4 = lane & 3;
    int wm = (wid >> 2) << 6;
    int wn = (wid & 3) << 5;

    float acc[4][4][4];
#pragma unroll
    for (int mt = 0; mt < 4; mt++)
#pragma unroll
        for (int nt = 0; nt < 4; nt++)
#pragma unroll
            for (int r = 0; r < 4; r++) acc[mt][nt][r] = 0.0f;

    const int T = 8;
    {
        uint32_t b = smb;
        cp16(b + o0, pA0h); cp16(b + o1, pA1h);
        cp16(b + o2, pA0l); cp16(b + o3, pA1l);
        cp16(b + o4, pB0h); cp16(b + o5, pB1h);
        cp16(b + o6, pB0l); cp16(b + o7, pB1l);
        CP_COMMIT();
    }
    for (int kt = 0; kt < T; kt++) {
        int s = kt & 1;
        if (kt + 1 < T) {
            int ko = (kt + 1) << 4;
            uint32_t b = smb + (uint32_t)((s ^ 1) * STAGE * 4);
            cp16(b + o0, pA0h + ko); cp16(b + o1, pA1h + ko);
            cp16(b + o2, pA0l + ko); cp16(b + o3, pA1l + ko);
            cp16(b + o4, pB0h + ko); cp16(b + o5, pB1h + ko);
            cp16(b + o6, pB0l + ko); cp16(b + o7, pB1l + ko);
            CP_COMMIT();
            CP_WAIT1();
        } else {
            CP_WAIT0();
        }
        __syncthreads();
        const float* S = smf + s * STAGE;
#pragma unroll
        for (int k8 = 0; k8 < 16; k8 += 8) {
            unsigned ah[4][4], al[4][4];
#pragma unroll
            for (int mt = 0; mt < 4; mt++) {
                int r0i = (wm + (mt << 4) + gid) * 20 + k8 + t4;
                int r1i = (wm + (mt << 4) + gid + 8) * 20 + k8 + t4;
                ah[mt][0] = __float_as_uint(S[r0i]);
                ah[mt][1] = __float_as_uint(S[r1i]);
                ah[mt][2] = __float_as_uint(S[r0i + 4]);
                ah[mt][3] = __float_as_uint(S[r1i + 4]);
                al[mt][0] = __float_as_uint(S[PLANE + r0i]);
                al[mt][1] = __float_as_uint(S[PLANE + r1i]);
                al[mt][2] = __float_as_uint(S[PLANE + r0i + 4]);
                al[mt][3] = __float_as_uint(S[PLANE + r1i + 4]);
            }
            unsigned bh[4][2], bl[4][2];
#pragma unroll
            for (int nt = 0; nt < 4; nt++) {
                int ci = (wn + (nt << 3) + gid) * 20 + k8 + t4;
                bh[nt][0] = __float_as_uint(S[2 * PLANE + ci]);
                bh[nt][1] = __float_as_uint(S[2 * PLANE + ci + 4]);
                bl[nt][0] = __float_as_uint(S[3 * PLANE + ci]);
                bl[nt][1] = __float_as_uint(S[3 * PLANE + ci + 4]);
            }
#pragma unroll
            for (int mt = 0; mt < 4; mt++)
#pragma unroll
                for (int nt = 0; nt < 4; nt++) {
                    MMA_TF32(acc[mt][nt], ah[mt], bh[nt]);
                    MMA_TF32(acc[mt][nt], ah[mt], bl[nt]);
                    MMA_TF32(acc[mt][nt], al[mt], bh[nt]);
                }
        }
        __syncthreads();
    }

    float bvv[4][2];
#pragma unroll
    for (int mt = 0; mt < 4; mt++) {
        bvv[mt][0] = b2[v0 + wm + (mt << 4) + gid];
        bvv[mt][1] = b2[v0 + wm + (mt << 4) + gid + 8];
    }
#pragma unroll
    for (int mt = 0; mt < 4; mt++)
#pragma unroll
        for (int nt = 0; nt < 4; nt++) {
            acc[mt][nt][0] += bvv[mt][0];
            acc[mt][nt][1] += bvv[mt][0];
            acc[mt][nt][2] += bvv[mt][1];
            acc[mt][nt][3] += bvv[mt][1];
        }

#pragma unroll
    for (int nt = 0; nt < 4; nt++) {
#pragma unroll
        for (int c = 0; c < 2; c++) {
            float lm = -1e30f;
            int la = 0;
#pragma unroll
            for (int mt = 0; mt < 4; mt++)
#pragma unroll
                for (int ro = 0; ro < 2; ro++) {
                    float lg = acc[mt][nt][ro * 2 + c];
                    if (lg > lm) {
                        lm = lg;
                        la = v0 + wm + (mt << 4) + gid + ro * 8;
                    }
                }
#pragma unroll
            for (int off = 4; off <= 16; off <<= 1) {
                float om = __shfl_xor_sync(0xffffffffu, lm, off);
                int oa = __shfl_xor_sync(0xffffffffu, la, off);
                if (om > lm || (om == lm && oa < la)) { lm = om; la = oa; }
            }
            if (gid == 0) {
                int tcol = wn + (nt << 3) + (t4 << 1) + c;
                wmax[(wm >> 6) * 128 + tcol] = lm;
                warg[(wm >> 6) * 128 + tcol] = la;
            }
        }
    }
    __syncthreads();
    float fm = 0.0f;
    int fa = 0;
    if (tid < 128) {
        float ma = wmax[tid], mb = wmax[128 + tid];
        if (mb > ma) { fm = mb; fa = warg[128 + tid]; }
        else { fm = ma; fa = warg[tid]; }
        bmx[tid] = fm;
    }
    __syncthreads();

#pragma unroll
    for (int nt = 0; nt < 4; nt++) {
#pragma unroll
        for (int c = 0; c < 2; c++) {
            int tcol = wn + (nt << 3) + (t4 << 1) + c;
            float mx = bmx[tcol];
            float s = 0.0f;
#pragma unroll
            for (int mt = 0; mt < 4; mt++)
#pragma unroll
                for (int ro = 0; ro < 2; ro++)
                    s += __expf(acc[mt][nt][ro * 2 + c] - mx);
#pragma unroll
            for (int off = 4; off <= 16; off <<= 1)
                s += __shfl_xor_sync(0xffffffffu, s, off);
            if (gid == 0) wsum[(wm >> 6) * 128 + tcol] = s;
        }
    }
    __syncthreads();
    if (tid < 128) {
        size_t tok = (size_t)(n0 + tid);
        g_pmax[tok * NVT + vt] = fm;
        g_parg[tok * NVT + vt] = fa;
        g_psum[tok * NVT + vt] = wsum[tid] + wsum[128 + tid];
    }
}

// ------------------ persistent BiLSTM scan v5: fused, 1 barrier/step -------
// 128 blocks x 256 threads. Block = (dir, 8-wide j-slice): all 4 gates,
// all 32 batches, full K=512 via mma 3xTF32. Whh slice (32 rows x 512 hi/lo)
// persistent in smem; h staged in 4 k-chunks (double-buffered cp.async).
// Gate fragments exchanged via block smem; c/h in registers; h planes
// double-buffered by step parity -> ONE grid barrier per step.
__global__ __launch_bounds__(256) void k_scan5(const float* __restrict__ gx,
                                               const float* __restrict__ mask,
                                               float* __restrict__ out,
                                               const float* __restrict__ whh_h,
                                               const float* __restrict__ whh_l) {
    extern __shared__ float sm[];
    uint32_t smb = (uint32_t)__cvta_generic_to_shared(sm);

    int tid = threadIdx.x;
    int bid = blockIdx.x;
    int d = bid >> 6;
    int jt = bid & 63;
    int j0 = jt << 3;

    // preload weight slice: 32 rows (g*8+jl -> global g*512+j0+jl) x 512, hi+lo
    {
        int r = tid >> 3;
        int seg = (tid & 7) << 6;
        int grow = ((r >> 3) << 9) + j0 + (r & 7);
        const float* srch = whh_h + ((size_t)(d * NG + grow) << 9) + seg;
        const float* srcl = whh_l + ((size_t)(d * NG + grow) << 9) + seg;
        float* dsth = sm + SC_WH + r * 516 + seg;
        float* dstl = sm + SC_WL + r * 516 + seg;
#pragma unroll
        for (int q = 0; q < 16; q++) {
            *(float4*)(dsth + q * 4) = __ldg((const float4*)(srch + q * 4));
            *(float4*)(dstl + q * 4) = __ldg((const float4*)(srcl + q * 4));
        }
    }

    int wid = tid >> 5, lane = tid & 31;
    int gid = lane >> 2, t4 = lane & 3;
    int m0 = (wid >> 2) << 4;       // 0 / 16
    int n0w = (wid & 3) << 3;       // 0,8,16,24

    // combine role: thread owns (b=cb, j=j0+ji)
    int cb = lane;
    int ji = wid;
    int cj = j0 + ji;
    float creg = 0.0f, hreg = 0.0f;

    __syncthreads();

    for (int s = 0; s < NL; s++) {
        int t = d ? (NL - 1 - s) : s;
        int p = s & 1;
        const float* hsrc_h = g_hph + (((size_t)(p * 2 + d) * NB) << 9);
        const float* hsrc_l = g_hpl + (((size_t)(p * 2 + d) * NB) << 9);

        // stage chunk 0 into buf 0
        {
            int idx = tid;
#pragma unroll
            for (int j = 0; j < 8; j++, idx += 256) {
                int pl = idx >> 10;
                int rem = idx & 1023;
                int row = rem >> 5;
                int c4 = (rem & 31) << 2;
                const float* src = (pl ? hsrc_l : hsrc_h) + (row << 9) + c4;
                uint32_t dst = smb + (uint32_t)((SC_HB + pl * 4224 + row * 132 + c4) << 2);
                cp16(dst, src);
            }
            CP_COMMIT();
        }

        float acc[4] = {0.0f, 0.0f, 0.0f, 0.0f};

#pragma unroll
        for (int ch = 0; ch < 4; ch++) {
            if (ch < 3) {
                // prefetch chunk ch+1 into buf (ch+1)&1
                int buf = (ch + 1) & 1;
                int ko = (ch + 1) << 7;
                int idx = tid;
#pragma unroll
                for (int j = 0; j < 8; j++, idx += 256) {
                    int pl = idx >> 10;
                    int rem = idx & 1023;
                    int row = rem >> 5;
                    int c4 = (rem & 31) << 2;
                    const float* src = (pl ? hsrc_l : hsrc_h) + (row << 9) + ko + c4;
                    uint32_t dst = smb + (uint32_t)((SC_HB + buf * 8448 + pl * 4224 + row * 132 + c4) << 2);
                    cp16(dst, src);
                }
                CP_COMMIT();
                CP_WAIT1();
            } else {
                CP_WAIT0();
            }
            __syncthreads();

            const float* Hh = sm + SC_HB + (ch & 1) * 8448;
            const float* Hl = Hh + 4224;
            const float* Whp = sm + SC_WH + (ch << 7);
            const float* Wlp = sm + SC_WL + (ch << 7);

#pragma unroll
            for (int k8 = 0; k8 < 16; k8++) {
                int kk = (k8 << 3) + t4;
                int r0 = (m0 + gid) * 516 + kk;
                int r1 = r0 + 8 * 516;
                unsigned ah[4], al[4];
                ah[0] = __float_as_uint(Whp[r0]);
                ah[1] = __float_as_uint(Whp[r1]);
                ah[2] = __float_as_uint(Whp[r0 + 4]);
                ah[3] = __float_as_uint(Whp[r1 + 4]);
                al[0] = __float_as_uint(Wlp[r0]);
                al[1] = __float_as_uint(Wlp[r1]);
                al[2] = __float_as_uint(Wlp[r0 + 4]);
                al[3] = __float_as_uint(Wlp[r1 + 4]);
                int ci = (n0w + gid) * 132 + kk;
                unsigned bh[2], bl[2];
                bh[0] = __float_as_uint(Hh[ci]);
                bh[1] = __float_as_uint(Hh[ci + 4]);
                bl[0] = __float_as_uint(Hl[ci]);
                bl[1] = __float_as_uint(Hl[ci + 4]);
                MMA_TF32(acc, ah, bh);
                MMA_TF32(acc, ah, bl);
                MMA_TF32(acc, al, bh);
            }
            __syncthreads();   // protect buffer reuse
        }

        // exchange gate fragments via smem
        float* Gs = sm + SC_GS;
        {
            int col = n0w + (t4 << 1);
            Gs[(m0 + gid) * 33 + col] = acc[0];
            Gs[(m0 + gid) * 33 + col + 1] = acc[1];
            Gs[(m0 + gid + 8) * 33 + col] = acc[2];
            Gs[(m0 + gid + 8) * 33 + col + 1] = acc[3];
        }
        __syncthreads();

        // combine
        {
            const float* gxr = gx + ((size_t)d * NTOK + (size_t)cb * NL + t) * NG;
            float g0 = __ldg(&gxr[0 * NH + cj]) + Gs[(0 * 8 + ji) * 33 + cb];
            float g1 = __ldg(&gxr[1 * NH + cj]) + Gs[(1 * 8 + ji) * 33 + cb];
            float g2 = __ldg(&gxr[2 * NH + cj]) + Gs[(2 * 8 + ji) * 33 + cb];
            float g3 = __ldg(&gxr[3 * NH + cj]) + Gs[(3 * 8 + ji) * 33 + cb];
            float cn = sigf(g1) * creg + sigf(g0) * tanhf_fast(g2);
            float hn = sigf(g3) * tanhf_fast(cn);
            float mt = mask[cb * NL + t];
            hreg = hreg + (hn - hreg) * mt;
            creg = creg + (cn - creg) * mt;
            out[((size_t)cb * NL + t) * 1024 + (d << 9) + cj] = hreg;
            float hh, hl;
            tf32split(hreg, hh, hl);
            size_t hidx = ((size_t)(((p ^ 1) * 2 + d) * NB + cb) << 9) + cj;
            g_hph[hidx] = hh;
            g_hpl[hidx] = hl;
        }
        __threadfence();
        gridbar();
    }
}

// ------------------ per-token combine ------------------
__global__ __launch_bounds__(256) void k_comb(const float* __restrict__ w2,
                                              const float* __restrict__ b2,
                                              const int* __restrict__ tgt,
                                              const float* __restrict__ cew,
                                              float* __restrict__ dout) {
    int warp = threadIdx.x >> 5, lane = threadIdx.x & 31;
    int m = blockIdx.x * 8 + warp;

    float lm = -1e30f, ls = 0.0f;
    int la = 0;
    for (int vt = lane; vt < NVT; vt += 32) {
        float tmx = g_pmax[(size_t)m * NVT + vt];
        float tsm = g_psum[(size_t)m * NVT + vt];
        int tag = g_parg[(size_t)m * NVT + vt];
        if (tmx > lm) {
            ls = ls * __expf(lm - tmx) + tsm;
            lm = tmx;
            la = tag;
        } else {
            ls += tsm * __expf(tmx - lm);
        }
    }
#pragma unroll
    for (int off = 16; off; off >>= 1) {
        float om = __shfl_down_sync(0xffffffffu, lm, off);
        float os = __shfl_down_sync(0xffffffffu, ls, off);
        int oa = __shfl_down_sync(0xffffffffu, la, off);
        float nm = fmaxf(lm, om);
        float ns = ls * __expf(lm - nm) + os * __expf(om - nm);
        int na = (om > lm) ? oa : ((om == lm && oa < la) ? oa : la);
        lm = nm; ls = ns; la = na;
    }

    int tg = tgt[m];
    float4 hv = *(const float4*)&g_hid[(size_t)m * 128 + lane * 4];
    float4 wv = *(const float4*)&w2[(size_t)tg * 128 + lane * 4];
    float dp = hv.x * wv.x + hv.y * wv.y + hv.z * wv.z + hv.w * wv.w;
#pragma unroll
    for (int off = 16; off; off >>= 1) dp += __shfl_down_sync(0xffffffffu, dp, off);

    if (lane == 0) {
        float logit_t = dp + b2[tg];
        float lse = lm + logf(ls);
        float nll = lse - logit_t;
        float w = cew[tg];
        g_nllw[m] = nll * w;
        g_wtok[m] = w;
        dout[1 + m] = (float)la;
    }
}

// ------------------ final loss reduce ------------------
__global__ __launch_bounds__(256) void k_loss(float* __restrict__ dout) {
    __shared__ float s1[256];
    __shared__ float s2[256];
    int tid = threadIdx.x;
    float a = 0.0f, b = 0.0f;
    for (int i = tid; i < NTOK; i += 256) { a += g_nllw[i]; b += g_wtok[i]; }
    s1[tid] = a; s2[tid] = b;
    __syncthreads();
    for (int off = 128; off; off >>= 1) {
        if (tid < off) { s1[tid] += s1[tid + off]; s2[tid] += s2[tid + off]; }
        __syncthreads();
    }
    if (tid == 0) dout[0] = s1[0] / s2[0];
}

// ------------------ launch ------------------
extern "C" void kernel_launch(void* const* d_in, const int* in_sizes, int n_in,
                              void* d_out, int out_size) {
    const int* inp_word = (const int*)d_in[0];
    const float* inp_mask = (const float*)d_in[1];
    const int* tgt_word = (const int*)d_in[3];
    const float* emb = (const float*)d_in[4];
    const float* w_ih0 = (const float*)d_in[5];
    const float* w_hh0 = (const float*)d_in[6];
    const float* b0 = (const float*)d_in[7];
    const float* w_ih = (const float*)d_in[8];
    const float* w_hh = (const float*)d_in[9];
    const float* bb = (const float*)d_in[10];
    const float* dec_w1 = (const float*)d_in[11];
    const float* dec_b1 = (const float*)d_in[12];
    const float* dec_w2 = (const float*)d_in[13];
    const float* dec_b2 = (const float*)d_in[14];
    const float* cew = (const float*)d_in[15];
    float* out = (float*)d_out;

    float *pgx, *pA, *pB, *phid, *pwh, *pwl, *pah, *pal, *pwhh, *pwhl;
    cudaGetSymbolAddress((void**)&pgx, g_gx);
    cudaGetSymbolAddress((void**)&pA, g_bufA);
    cudaGetSymbolAddress((void**)&pB, g_bufB);
    cudaGetSymbolAddress((void**)&phid, g_hid);
    cudaGetSymbolAddress((void**)&pwh, g_wh);
    cudaGetSymbolAddress((void**)&pwl, g_wl);
    cudaGetSymbolAddress((void**)&pah, g_ah);
    cudaGetSymbolAddress((void**)&pal, g_al);
    cudaGetSymbolAddress((void**)&pwhh, g_whhh);
    cudaGetSymbolAddress((void**)&pwhl, g_whhl);

    const int gsm = 2 * STAGE * 4;     // 81920 bytes
    const int ssm = SC_TOT * 4;        // 203904 bytes
    cudaFuncSetAttribute(k_gemm2, cudaFuncAttributeMaxDynamicSharedMemorySize, gsm);
    cudaFuncSetAttribute(k_dec2m, cudaFuncAttributeMaxDynamicSharedMemorySize, gsm);
    cudaFuncSetAttribute(k_scan5, cudaFuncAttributeMaxDynamicSharedMemorySize, ssm);

    // 0. split all weights into tf32 hi/lo planes
    k_split<<<512, 256>>>(w_ih0, pwh + OFF_WIH0, pwl + OFF_WIH0, 524288 / 4);
    k_split<<<8192, 256>>>(w_ih, pwh + OFF_WIH1, pwl + OFF_WIH1, 8388608 / 4);
    k_split<<<128, 256>>>(dec_w1, pwh + OFF_W1, pwl + OFF_W1, 131072 / 4);
    k_split<<<4000, 256>>>(dec_w2, pwh + OFF_W2, pwl + OFF_W2, 4096000 / 4);
    k_split<<<2048, 256>>>(w_hh0, pwhh, pwhl, 2097152 / 4);
    k_split<<<4096, 256>>>(w_hh, pwhh + 2097152, pwhl + 2097152, 4194304 / 4);

    // 1. embedding (split planes, K=128)
    k_embed<<<(NTOK * NE) / 256, 256>>>(inp_word, emb);

    // 2. layer 0
    k_gemm2<<<dim3(NG / 128, NTOK / 128, 2), 256, gsm>>>(
        pah, pal, pwh + OFF_WIH0, pwl + OFF_WIH0, b0, pgx,
        NE, NG, (long long)NG * NE, NG, (long long)NTOK * NG, 0);
    k_zero<<<128, 256>>>();
    k_scan5<<<128, 256, ssm>>>(pgx, inp_mask, pA, pwhh, pwhl);

    // 3. layer 1
    k_split<<<4096, 256>>>(pA, pah, pal, (NTOK * 1024) / 4);
    k_gemm2<<<dim3(NG / 128, NTOK / 128, 2), 256, gsm>>>(
        pah, pal, pwh + OFF_WIH1, pwl + OFF_WIH1, bb, pgx,
        1024, NG, (long long)NG * 1024, NG, (long long)NTOK * NG, 0);
    k_zero<<<128, 256>>>();
    k_scan5<<<128, 256, ssm>>>(pgx, inp_mask, pB, pwhh + 2097152, pwhl + 2097152);

    // 4. layer 2
    k_split<<<4096, 256>>>(pB, pah, pal, (NTOK * 1024) / 4);
    k_gemm2<<<dim3(NG / 128, NTOK / 128, 2), 256, gsm>>>(
        pah, pal, pwh + OFF_WIH1 + 4194304, pwl + OFF_WIH1 + 4194304,
        bb + 2 * NG, pgx,
        1024, NG, (long long)NG * 1024, NG, (long long)NTOK * NG, 0);
    k_zero<<<128, 256>>>();
    k_scan5<<<128, 256, ssm>>>(pgx, inp_mask, pA, pwhh + 4194304, pwhl + 4194304);

    // 5. decoder layer 1 (relu, writes g_hid + split planes)
    k_split<<<4096, 256>>>(pA, pah, pal, (NTOK * 1024) / 4);
    k_gemm2<<<dim3(1, NTOK / 128, 1), 256, gsm>>>(
        pah, pal, pwh + OFF_W1, pwl + OFF_W1, dec_b1, phid,
        1024, 128, 0, 0, 0, 2);

    // 6. decoder layer 2 (mma) + fused online softmax partials
    k_dec2m<<<dim3(NVT, NTOK / 128), 256, gsm>>>(dec_b2);

    // 7. per-token combine
    k_comb<<<NTOK / 8, 256>>>(dec_w2, dec_b2, tgt_word, cew, out);

    // 8. loss reduce
    k_loss<<<1, 256>>>(out);
}

// round 10
// speedup vs baseline: 1.0291x; 1.0291x over previous
#include <cuda_runtime.h>
#include <math.h>
#include <stdint.h>

#define NB 32
#define NL 128
#define NH 512
#define NG 2048
#define NV 32000
#define NE 128
#define NTOK 4096
#define NVT 250

// weight-plane arena offsets (floats)
#define OFF_WIH0 0
#define OFF_WIH1 524288
#define OFF_W1   8912896
#define OFF_W2   9043968
#define WARENA   13139968

// ------------------ scratch ------------------
__device__ float g_wh[WARENA];
__device__ float g_wl[WARENA];
__device__ float g_whhh[3 * 2 * NG * NH];
__device__ float g_whhl[3 * 2 * NG * NH];
__device__ float g_ah[NTOK * 1024];
__device__ float g_al[NTOK * 1024];
__device__ float g_gx[2u * NTOK * NG];          // [dir][m][g], m = b*128+t
__device__ float g_hid[NTOK * 128];
__device__ float g_hidh[NTOK * 128];
__device__ float g_hidl[NTOK * 128];
__device__ float g_hph[2 * NB * NH];
__device__ float g_hpl[2 * NB * NH];
__device__ float g_part[2 * 4 * NG * NB];       // [dir][ks][g][b]
__device__ float g_pmax[(size_t)NTOK * NVT];
__device__ float g_psum[(size_t)NTOK * NVT];
__device__ int   g_parg[(size_t)NTOK * NVT];
__device__ float g_nllw[NTOK];
__device__ float g_wtok[NTOK];
__device__ unsigned int g_barcnt2[2];

// ------------------ helpers ------------------
__device__ __forceinline__ float sigf(float x) {
    return 1.0f / (1.0f + __expf(-x));
}
__device__ __forceinline__ float tanhf_fast(float x) {
    float e = __expf(-2.0f * fabsf(x));
    float r = (1.0f - e) / (1.0f + e);
    return copysignf(r, x);
}

// per-direction grid barrier over 64 blocks: release/acquire, no membar
__device__ __forceinline__ void gridbar_d(int d) {
    __syncthreads();
    if (threadIdx.x == 0) {
        unsigned int* ctr = &g_barcnt2[d];
        unsigned int t;
        asm volatile("atom.add.release.gpu.u32 %0, [%1], 1;"
                     : "=r"(t) : "l"(ctr) : "memory");
        unsigned int need = ((t >> 6) + 1u) << 6;
        unsigned int cur;
        do {
            asm volatile("ld.acquire.gpu.u32 %0, [%1];"
                         : "=r"(cur) : "l"(ctr) : "memory");
        } while (cur < need);
    }
    __syncthreads();
}

__device__ __forceinline__ void tf32split(float x, float& hi, float& lo) {
    unsigned hb;
    asm("cvt.rna.tf32.f32 %0, %1;" : "=r"(hb) : "f"(x));
    float hf = __uint_as_float(hb);
    float l = x - hf;
    unsigned lb;
    asm("cvt.rna.tf32.f32 %0, %1;" : "=r"(lb) : "f"(l));
    hi = hf;
    lo = __uint_as_float(lb);
}

#define MMA_TF32(c, a, b)                                                     \
    asm volatile(                                                             \
        "mma.sync.aligned.m16n8k8.row.col.f32.tf32.tf32.f32 "                 \
        "{%0,%1,%2,%3}, {%4,%5,%6,%7}, {%8,%9}, {%0,%1,%2,%3};"               \
        : "+f"((c)[0]), "+f"((c)[1]), "+f"((c)[2]), "+f"((c)[3])              \
        : "r"((a)[0]), "r"((a)[1]), "r"((a)[2]), "r"((a)[3]),                 \
          "r"((b)[0]), "r"((b)[1]))

__device__ __forceinline__ void cp16(uint32_t dst, const float* src) {
    asm volatile("cp.async.cg.shared.global [%0], [%1], 16;" :: "r"(dst), "l"(src));
}
#define CP_COMMIT() asm volatile("cp.async.commit_group;")
#define CP_WAIT1()  asm volatile("cp.async.wait_group 1;")
#define CP_WAIT0()  asm volatile("cp.async.wait_group 0;")

// gemm stage layout: 4 planes (AH, AL, BH, BL) x 128 rows x 20 floats
#define PLANE 2560
#define STAGE 10240

// ------------------ split kernel (weights only now) ------------------
__global__ __launch_bounds__(256) void k_split(const float* __restrict__ s,
                                               float* __restrict__ dh,
                                               float* __restrict__ dl, int n4) {
    int i = blockIdx.x * 256 + threadIdx.x;
    if (i < n4) {
        float4 v = ((const float4*)s)[i];
        float4 h4, l4;
        tf32split(v.x, h4.x, l4.x);
        tf32split(v.y, h4.y, l4.y);
        tf32split(v.z, h4.z, l4.z);
        tf32split(v.w, h4.w, l4.w);
        ((float4*)dh)[i] = h4;
        ((float4*)dl)[i] = l4;
    }
}

// ------------------ embedding (writes split planes) ------------------
__global__ __launch_bounds__(256) void k_embed(const int* __restrict__ w,
                                               const float* __restrict__ emb) {
    int i = blockIdx.x * 256 + threadIdx.x;
    float v = emb[(size_t)w[i >> 7] * NE + (i & 127)];
    float h, l;
    tf32split(v, h, l);
    g_ah[i] = h;
    g_al[i] = l;
}

// ------------------ zero h planes + barrier counters ------------------
__global__ __launch_bounds__(256) void k_zero() {
    int i = blockIdx.x * 256 + threadIdx.x;
    if (i < 2 * NB * NH) { g_hph[i] = 0.0f; g_hpl[i] = 0.0f; }
    if (i < 2) g_barcnt2[i] = 0u;
}

// ------------------ 3xTF32 mma GEMM, presplit inputs, cp.async pipeline ----
__global__ __launch_bounds__(256) void k_gemm2(const float* __restrict__ Ahp,
                                               const float* __restrict__ Alp,
                                               const float* __restrict__ Whp,
                                               const float* __restrict__ Wlp,
                                               const float* __restrict__ bias,
                                               float* __restrict__ C,
                                               int K, int N,
                                               long long wStr, long long bStr,
                                               long long cStr, int mode) {
    extern __shared__ float smf[];
    uint32_t smb = (uint32_t)__cvta_generic_to_shared(smf);

    int d = blockIdx.z;
    Whp += (size_t)d * wStr;
    Wlp += (size_t)d * wStr;
    bias += (size_t)d * bStr;
    C += (size_t)d * cStr;

    int tid = threadIdx.x;
    int m0 = blockIdx.y << 7, n0 = blockIdx.x << 7;
    int lr = tid >> 2, lkq = (tid & 3) << 2;

    const float* pA0h = Ahp + (size_t)(m0 + lr) * K + lkq;
    const float* pA1h = Ahp + (size_t)(m0 + lr + 64) * K + lkq;
    const float* pA0l = Alp + (size_t)(m0 + lr) * K + lkq;
    const float* pA1l = Alp + (size_t)(m0 + lr + 64) * K + lkq;
    const float* pB0h = Whp + (size_t)(n0 + lr) * K + lkq;
    const float* pB1h = Whp + (size_t)(n0 + lr + 64) * K + lkq;
    const float* pB0l = Wlp + (size_t)(n0 + lr) * K + lkq;
    const float* pB1l = Wlp + (size_t)(n0 + lr + 64) * K + lkq;

    uint32_t o0 = (uint32_t)((0 * PLANE + lr * 20 + lkq) * 4);
    uint32_t o1 = (uint32_t)((0 * PLANE + (lr + 64) * 20 + lkq) * 4);
    uint32_t o2 = (uint32_t)((1 * PLANE + lr * 20 + lkq) * 4);
    uint32_t o3 = (uint32_t)((1 * PLANE + (lr + 64) * 20 + lkq) * 4);
    uint32_t o4 = (uint32_t)((2 * PLANE + lr * 20 + lkq) * 4);
    uint32_t o5 = (uint32_t)((2 * PLANE + (lr + 64) * 20 + lkq) * 4);
    uint32_t o6 = (uint32_t)((3 * PLANE + lr * 20 + lkq) * 4);
    uint32_t o7 = (uint32_t)((3 * PLANE + (lr + 64) * 20 + lkq) * 4);

    int wid = tid >> 5, lane = tid & 31;
    int gid = lane >> 2, t4 = lane & 3;
    int wm = (wid >> 2) << 6;
    int wn = (wid & 3) << 5;

    float acc[4][4][4];
#pragma unroll
    for (int mt = 0; mt < 4; mt++)
#pragma unroll
        for (int nt = 0; nt < 4; nt++)
#pragma unroll
            for (int r = 0; r < 4; r++) acc[mt][nt][r] = 0.0f;

    int T = K >> 4;
    {
        uint32_t b = smb;
        cp16(b + o0, pA0h); cp16(b + o1, pA1h);
        cp16(b + o2, pA0l); cp16(b + o3, pA1l);
        cp16(b + o4, pB0h); cp16(b + o5, pB1h);
        cp16(b + o6, pB0l); cp16(b + o7, pB1l);
        CP_COMMIT();
    }

    for (int kt = 0; kt < T; kt++) {
        int s = kt & 1;
        if (kt + 1 < T) {
            int ko = (kt + 1) << 4;
            uint32_t b = smb + (uint32_t)((s ^ 1) * STAGE * 4);
            cp16(b + o0, pA0h + ko); cp16(b + o1, pA1h + ko);
            cp16(b + o2, pA0l + ko); cp16(b + o3, pA1l + ko);
            cp16(b + o4, pB0h + ko); cp16(b + o5, pB1h + ko);
            cp16(b + o6, pB0l + ko); cp16(b + o7, pB1l + ko);
            CP_COMMIT();
            CP_WAIT1();
        } else {
            CP_WAIT0();
        }
        __syncthreads();
        const float* S = smf + s * STAGE;

#pragma unroll
        for (int k8 = 0; k8 < 16; k8 += 8) {
            unsigned ah[4][4], al[4][4];
#pragma unroll
            for (int mt = 0; mt < 4; mt++) {
                int r0i = (wm + (mt << 4) + gid) * 20 + k8 + t4;
                int r1i = (wm + (mt << 4) + gid + 8) * 20 + k8 + t4;
                ah[mt][0] = __float_as_uint(S[r0i]);
                ah[mt][1] = __float_as_uint(S[r1i]);
                ah[mt][2] = __float_as_uint(S[r0i + 4]);
                ah[mt][3] = __float_as_uint(S[r1i + 4]);
                al[mt][0] = __float_as_uint(S[PLANE + r0i]);
                al[mt][1] = __float_as_uint(S[PLANE + r1i]);
                al[mt][2] = __float_as_uint(S[PLANE + r0i + 4]);
                al[mt][3] = __float_as_uint(S[PLANE + r1i + 4]);
            }
            unsigned bh[4][2], bl[4][2];
#pragma unroll
            for (int nt = 0; nt < 4; nt++) {
                int ci = (wn + (nt << 3) + gid) * 20 + k8 + t4;
                bh[nt][0] = __float_as_uint(S[2 * PLANE + ci]);
                bh[nt][1] = __float_as_uint(S[2 * PLANE + ci + 4]);
                bl[nt][0] = __float_as_uint(S[3 * PLANE + ci]);
                bl[nt][1] = __float_as_uint(S[3 * PLANE + ci + 4]);
            }
#pragma unroll
            for (int mt = 0; mt < 4; mt++)
#pragma unroll
                for (int nt = 0; nt < 4; nt++) {
                    MMA_TF32(acc[mt][nt], ah[mt], bh[nt]);
                    MMA_TF32(acc[mt][nt], ah[mt], bl[nt]);
                    MMA_TF32(acc[mt][nt], al[mt], bh[nt]);
                }
        }
        __syncthreads();
    }

#pragma unroll
    for (int mt = 0; mt < 4; mt++) {
#pragma unroll
        for (int nt = 0; nt < 4; nt++) {
            int m = m0 + wm + (mt << 4) + gid;
            int n = n0 + wn + (nt << 3) + (t4 << 1);
            float bv0 = bias[n], bv1 = bias[n + 1];
            float v0 = acc[mt][nt][0] + bv0;
            float v1 = acc[mt][nt][1] + bv1;
            float v2 = acc[mt][nt][2] + bv0;
            float v3 = acc[mt][nt][3] + bv1;
            if (mode) {
                v0 = fmaxf(v0, 0.0f); v1 = fmaxf(v1, 0.0f);
                v2 = fmaxf(v2, 0.0f); v3 = fmaxf(v3, 0.0f);
            }
            float2 p0 = {v0, v1};
            float2 p1 = {v2, v3};
            *(float2*)(C + (size_t)m * N + n) = p0;
            *(float2*)(C + (size_t)(m + 8) * N + n) = p1;
            if (mode == 2) {
                float h, l;
                size_t i0 = (size_t)m * N + n;
                size_t i1 = (size_t)(m + 8) * N + n;
                tf32split(v0, h, l); g_hidh[i0] = h;     g_hidl[i0] = l;
                tf32split(v1, h, l); g_hidh[i0 + 1] = h; g_hidl[i0 + 1] = l;
                tf32split(v2, h, l); g_hidh[i1] = h;     g_hidl[i1] = l;
                tf32split(v3, h, l); g_hidh[i1 + 1] = h; g_hidl[i1 + 1] = l;
            }
        }
    }
}

// ------------------ decoder2 mma: logits tile + online softmax partials ----
__global__ __launch_bounds__(256) void k_dec2m(const float* __restrict__ b2) {
    extern __shared__ float smf[];
    uint32_t smb = (uint32_t)__cvta_generic_to_shared(smf);
    __shared__ float wmax[256];
    __shared__ int   warg[256];
    __shared__ float wsum[256];
    __shared__ float bmx[128];

    const float* Ahp = g_wh + OFF_W2;
    const float* Alp = g_wl + OFF_W2;

    int tid = threadIdx.x;
    int vt = blockIdx.x;
    int v0 = vt << 7;
    int n0 = blockIdx.y << 7;
    int lr = tid >> 2, lkq = (tid & 3) << 2;
    const int K = 128;

    const float* pA0h = Ahp + (size_t)(v0 + lr) * K + lkq;
    const float* pA1h = Ahp + (size_t)(v0 + lr + 64) * K + lkq;
    const float* pA0l = Alp + (size_t)(v0 + lr) * K + lkq;
    const float* pA1l = Alp + (size_t)(v0 + lr + 64) * K + lkq;
    const float* pB0h = g_hidh + (size_t)(n0 + lr) * K + lkq;
    const float* pB1h = g_hidh + (size_t)(n0 + lr + 64) * K + lkq;
    const float* pB0l = g_hidl + (size_t)(n0 + lr) * K + lkq;
    const float* pB1l = g_hidl + (size_t)(n0 + lr + 64) * K + lkq;

    uint32_t o0 = (uint32_t)((0 * PLANE + lr * 20 + lkq) * 4);
    uint32_t o1 = (uint32_t)((0 * PLANE + (lr + 64) * 20 + lkq) * 4);
    uint32_t o2 = (uint32_t)((1 * PLANE + lr * 20 + lkq) * 4);
    uint32_t o3 = (uint32_t)((1 * PLANE + (lr + 64) * 20 + lkq) * 4);
    uint32_t o4 = (uint32_t)((2 * PLANE + lr * 20 + lkq) * 4);
    uint32_t o5 = (uint32_t)((2 * PLANE + (lr + 64) * 20 + lkq) * 4);
    uint32_t o6 = (uint32_t)((3 * PLANE + lr * 20 + lkq) * 4);
    uint32_t o7 = (uint32_t)((3 * PLANE + (lr + 64) * 20 + lkq) * 4);

    int wid = tid >> 5, lane = tid & 31;
    int gid = lane >> 2, t4 = lane & 3;
    int wm = (wid >> 2) << 6;
    int wn = (wid & 3) << 5;

    float acc[4][4][4];
#pragma unroll
    for (int mt = 0; mt < 4; mt++)
#pragma unroll
        for (int nt = 0; nt < 4; nt++)
#pragma unroll
            for (int r = 0; r < 4; r++) acc[mt][nt][r] = 0.0f;

    const int T = 8;
    {
        uint32_t b = smb;
        cp16(b + o0, pA0h); cp16(b + o1, pA1h);
        cp16(b + o2, pA0l); cp16(b + o3, pA1l);
        cp16(b + o4, pB0h); cp16(b + o5, pB1h);
        cp16(b + o6, pB0l); cp16(b + o7, pB1l);
        CP_COMMIT();
    }
    for (int kt = 0; kt < T; kt++) {
        int s = kt & 1;
        if (kt + 1 < T) {
            int ko = (kt + 1) << 4;
            uint32_t b = smb + (uint32_t)((s ^ 1) * STAGE * 4);
            cp16(b + o0, pA0h + ko); cp16(b + o1, pA1h + ko);
            cp16(b + o2, pA0l + ko); cp16(b + o3, pA1l + ko);
            cp16(b + o4, pB0h + ko); cp16(b + o5, pB1h + ko);
            cp16(b + o6, pB0l + ko); cp16(b + o7, pB1l + ko);
            CP_COMMIT();
            CP_WAIT1();
        } else {
            CP_WAIT0();
        }
        __syncthreads();
        const float* S = smf + s * STAGE;
#pragma unroll
        for (int k8 = 0; k8 < 16; k8 += 8) {
            unsigned ah[4][4], al[4][4];
#pragma unroll
            for (int mt = 0; mt < 4; mt++) {
                int r0i = (wm + (mt << 4) + gid) * 20 + k8 + t4;
                int r1i = (wm + (mt << 4) + gid + 8) * 20 + k8 + t4;
                ah[mt][0] = __float_as_uint(S[r0i]);
                ah[mt][1] = __float_as_uint(S[r1i]);
                ah[mt][2] = __float_as_uint(S[r0i + 4]);
                ah[mt][3] = __float_as_uint(S[r1i + 4]);
                al[mt][0] = __float_as_uint(S[PLANE + r0i]);
                al[mt][1] = __float_as_uint(S[PLANE + r1i]);
                al[mt][2] = __float_as_uint(S[PLANE + r0i + 4]);
                al[mt][3] = __float_as_uint(S[PLANE + r1i + 4]);
            }
            unsigned bh[4][2], bl[4][2];
#pragma unroll
            for (int nt = 0; nt < 4; nt++) {
                int ci = (wn + (nt << 3) + gid) * 20 + k8 + t4;
                bh[nt][0] = __float_as_uint(S[2 * PLANE + ci]);
                bh[nt][1] = __float_as_uint(S[2 * PLANE + ci + 4]);
                bl[nt][0] = __float_as_uint(S[3 * PLANE + ci]);
                bl[nt][1] = __float_as_uint(S[3 * PLANE + ci + 4]);
            }
#pragma unroll
            for (int mt = 0; mt < 4; mt++)
#pragma unroll
                for (int nt = 0; nt < 4; nt++) {
                    MMA_TF32(acc[mt][nt], ah[mt], bh[nt]);
                    MMA_TF32(acc[mt][nt], ah[mt], bl[nt]);
                    MMA_TF32(acc[mt][nt], al[mt], bh[nt]);
                }
        }
        __syncthreads();
    }

    float bvv[4][2];
#pragma unroll
    for (int mt = 0; mt < 4; mt++) {
        bvv[mt][0] = b2[v0 + wm + (mt << 4) + gid];
        bvv[mt][1] = b2[v0 + wm + (mt << 4) + gid + 8];
    }
#pragma unroll
    for (int mt = 0; mt < 4; mt++)
#pragma unroll
        for (int nt = 0; nt < 4; nt++) {
            acc[mt][nt][0] += bvv[mt][0];
            acc[mt][nt][1] += bvv[mt][0];
            acc[mt][nt][2] += bvv[mt][1];
            acc[mt][nt][3] += bvv[mt][1];
        }

#pragma unroll
    for (int nt = 0; nt < 4; nt++) {
#pragma unroll
        for (int c = 0; c < 2; c++) {
            float lm = -1e30f;
            int la = 0;
#pragma unroll
            for (int mt = 0; mt < 4; mt++)
#pragma unroll
                for (int ro = 0; ro < 2; ro++) {
                    float lg = acc[mt][nt][ro * 2 + c];
                    if (lg > lm) {
                        lm = lg;
                        la = v0 + wm + (mt << 4) + gid + ro * 8;
                    }
                }
#pragma unroll
            for (int off = 4; off <= 16; off <<= 1) {
                float om = __shfl_xor_sync(0xffffffffu, lm, off);
                int oa = __shfl_xor_sync(0xffffffffu, la, off);
                if (om > lm || (om == lm && oa < la)) { lm = om; la = oa; }
            }
            if (gid == 0) {
                int tcol = wn + (nt << 3) + (t4 << 1) + c;
                wmax[(wm >> 6) * 128 + tcol] = lm;
                warg[(wm >> 6) * 128 + tcol] = la;
            }
        }
    }
    __syncthreads();
    float fm = 0.0f;
    int fa = 0;
    if (tid < 128) {
        float ma = wmax[tid], mb = wmax[128 + tid];
        if (mb > ma) { fm = mb; fa = warg[128 + tid]; }
        else { fm = ma; fa = warg[tid]; }
        bmx[tid] = fm;
    }
    __syncthreads();

#pragma unroll
    for (int nt = 0; nt < 4; nt++) {
#pragma unroll
        for (int c = 0; c < 2; c++) {
            int tcol = wn + (nt << 3) + (t4 << 1) + c;
            float mx = bmx[tcol];
            float s = 0.0f;
#pragma unroll
            for (int mt = 0; mt < 4; mt++)
#pragma unroll
                for (int ro = 0; ro < 2; ro++)
                    s += __expf(acc[mt][nt][ro * 2 + c] - mx);
#pragma unroll
            for (int off = 4; off <= 16; off <<= 1)
                s += __shfl_xor_sync(0xffffffffu, s, off);
            if (gid == 0) wsum[(wm >> 6) * 128 + tcol] = s;
        }
    }
    __syncthreads();
    if (tid < 128) {
        size_t tok = (size_t)(n0 + tid);
        g_pmax[tok * NVT + vt] = fm;
        g_parg[tok * NVT + vt] = fa;
        g_psum[tok * NVT + vt] = wsum[tid] + wsum[128 + tid];
    }
}

// ------------------ persistent BiLSTM scan v4.1 (tensor core + fast bars) --
// Identical topology to v4 (proven): 128 blocks x 256 threads, k-split mma
// partials + combine, 2 per-direction barriers per step. Combine writes the
// sequence output directly as split hi/lo planes into g_ah/g_al.
__global__ __launch_bounds__(256) void k_scan4(const float* __restrict__ gx,
                                               const float* __restrict__ mask,
                                               const float* __restrict__ whh_h,
                                               const float* __restrict__ whh_l) {
    extern __shared__ float sm[];
    float* Wh = sm;                         // [128][132]
    float* Wl = sm + 16896;                 // [128][132]
    float* Hh = sm + 33792;                 // [32][132]
    float* Hl = sm + 33792 + 4224;          // [32][132]
    uint32_t smb = (uint32_t)__cvta_generic_to_shared(sm);

    int tid = threadIdx.x;
    int bid = blockIdx.x;
    int d = bid >> 6;
    int ks = (bid >> 4) & 3;
    int gt = bid & 15;
    int g0 = gt << 7;
    int k0 = ks << 7;

    // preload Whh hi/lo tile (once per layer)
#pragma unroll
    for (int p = 0; p < 2; p++) {
        const float* src = p ? whh_l : whh_h;
        float* dst = p ? Wl : Wh;
#pragma unroll
        for (int j = 0; j < 16; j++) {
            int idx = tid + j * 256;
            int row = idx >> 5;
            int c = (idx & 31) << 2;
            float4 v = __ldg((const float4*)(src + (size_t)(d * NG + g0 + row) * NH + k0 + c));
            *(float4*)&dst[row * 132 + c] = v;
        }
    }

    int wid = tid >> 5, lane = tid & 31;
    int gid = lane >> 2, t4 = lane & 3;
    int rowbase = wid << 4;

    // combine role
    int jt = bid & 63;
    int cb = tid & 31;
    int jl = tid >> 5;
    int cj = (jt << 3) + jl;
    float creg = 0.0f, hreg = 0.0f;

    __syncthreads();

    for (int s = 0; s < NL; s++) {
        int t = d ? (NL - 1 - s) : s;

        // ---- stage h planes via cp.async ----
        {
            int idx = tid;
#pragma unroll
            for (int j = 0; j < 8; j++, idx += 256) {
                int p = idx >> 10;
                int rem = idx & 1023;
                int row = rem >> 5;
                int c = (rem & 31) << 2;
                const float* src = (p ? g_hpl : g_hph) + (size_t)(d * NB + row) * NH + k0 + c;
                uint32_t dst = smb + (uint32_t)(((p ? 38016 : 33792) + row * 132 + c) * 4);
                cp16(dst, src);
            }
            CP_COMMIT();
            CP_WAIT0();
        }
        __syncthreads();

        // ---- mma partial: [128 gates] x [32 b] over k-slice ----
        float acc[4][4];
#pragma unroll
        for (int nt = 0; nt < 4; nt++)
#pragma unroll
            for (int r = 0; r < 4; r++) acc[nt][r] = 0.0f;

#pragma unroll
        for (int k8 = 0; k8 < 16; k8++) {
            int kk = (k8 << 3) + t4;
            int r0 = (rowbase + gid) * 132 + kk;
            int r1 = r0 + 8 * 132;
            unsigned ah[4], al[4];
            ah[0] = __float_as_uint(Wh[r0]);
            ah[1] = __float_as_uint(Wh[r1]);
            ah[2] = __float_as_uint(Wh[r0 + 4]);
            ah[3] = __float_as_uint(Wh[r1 + 4]);
            al[0] = __float_as_uint(Wl[r0]);
            al[1] = __float_as_uint(Wl[r1]);
            al[2] = __float_as_uint(Wl[r0 + 4]);
            al[3] = __float_as_uint(Wl[r1 + 4]);
#pragma unroll
            for (int nt = 0; nt < 4; nt++) {
                int ci = ((nt << 3) + gid) * 132 + kk;
                unsigned bh[2], bl[2];
                bh[0] = __float_as_uint(Hh[ci]);
                bh[1] = __float_as_uint(Hh[ci + 4]);
                bl[0] = __float_as_uint(Hl[ci]);
                bl[1] = __float_as_uint(Hl[ci + 4]);
                MMA_TF32(acc[nt], ah, bh);
                MMA_TF32(acc[nt], ah, bl);
                MMA_TF32(acc[nt], al, bh);
            }
        }

        // ---- store partials ----
        {
            size_t pbase = ((size_t)(d * 4 + ks) * NG + g0) * NB;
            int grow = rowbase + gid;
#pragma unroll
            for (int nt = 0; nt < 4; nt++) {
                int b = (nt << 3) + (t4 << 1);
                float2 p0 = {acc[nt][0], acc[nt][1]};
                float2 p1 = {acc[nt][2], acc[nt][3]};
                *(float2*)&g_part[pbase + (size_t)grow * NB + b] = p0;
                *(float2*)&g_part[pbase + (size_t)(grow + 8) * NB + b] = p1;
            }
        }
        gridbar_d(d);

        // ---- combine: one (b, j) per thread ----
        {
            float gate[4];
            const float* gxr = gx + ((size_t)d * NTOK + (size_t)cb * NL + t) * NG;
#pragma unroll
            for (int gi = 0; gi < 4; gi++) {
                int g = gi * NH + cj;
                float v = __ldg(&gxr[g]);
#pragma unroll
                for (int kss = 0; kss < 4; kss++)
                    v += __ldcg(&g_part[((size_t)(d * 4 + kss) * NG + g) * NB + cb]);
                gate[gi] = v;
            }
            float cn = sigf(gate[1]) * creg + sigf(gate[0]) * tanhf_fast(gate[2]);
            float hn = sigf(gate[3]) * tanhf_fast(cn);
            float mt = mask[cb * NL + t];
            hreg = hreg + (hn - hreg) * mt;
            creg = creg + (cn - creg) * mt;
            float hh, hl;
            tf32split(hreg, hh, hl);
            size_t hidx = (size_t)(d * NB + cb) * NH + cj;
            g_hph[hidx] = hh;
            g_hpl[hidx] = hl;
            // fused split sequence output (next layer's A planes)
            size_t oidx = ((size_t)cb * NL + t) * 1024 + (d << 9) + cj;
            g_ah[oidx] = hh;
            g_al[oidx] = hl;
        }
        gridbar_d(d);
    }
}

// ------------------ per-token combine ------------------
__global__ __launch_bounds__(256) void k_comb(const float* __restrict__ w2,
                                              const float* __restrict__ b2,
                                              const int* __restrict__ tgt,
                                              const float* __restrict__ cew,
                                              float* __restrict__ dout) {
    int warp = threadIdx.x >> 5, lane = threadIdx.x & 31;
    int m = blockIdx.x * 8 + warp;

    float lm = -1e30f, ls = 0.0f;
    int la = 0;
    for (int vt = lane; vt < NVT; vt += 32) {
        float tmx = g_pmax[(size_t)m * NVT + vt];
        float tsm = g_psum[(size_t)m * NVT + vt];
        int tag = g_parg[(size_t)m * NVT + vt];
        if (tmx > lm) {
            ls = ls * __expf(lm - tmx) + tsm;
            lm = tmx;
            la = tag;
        } else {
            ls += tsm * __expf(tmx - lm);
        }
    }
#pragma unroll
    for (int off = 16; off; off >>= 1) {
        float om = __shfl_down_sync(0xffffffffu, lm, off);
        float os = __shfl_down_sync(0xffffffffu, ls, off);
        int oa = __shfl_down_sync(0xffffffffu, la, off);
        float nm = fmaxf(lm, om);
        float ns = ls * __expf(lm - nm) + os * __expf(om - nm);
        int na = (om > lm) ? oa : ((om == lm && oa < la) ? oa : la);
        lm = nm; ls = ns; la = na;
    }

    int tg = tgt[m];
    float4 hv = *(const float4*)&g_hid[(size_t)m * 128 + lane * 4];
    float4 wv = *(const float4*)&w2[(size_t)tg * 128 + lane * 4];
    float dp = hv.x * wv.x + hv.y * wv.y + hv.z * wv.z + hv.w * wv.w;
#pragma unroll
    for (int off = 16; off; off >>= 1) dp += __shfl_down_sync(0xffffffffu, dp, off);

    if (lane == 0) {
        float logit_t = dp + b2[tg];
        float lse = lm + logf(ls);
        float nll = lse - logit_t;
        float w = cew[tg];
        g_nllw[m] = nll * w;
        g_wtok[m] = w;
        dout[1 + m] = (float)la;
    }
}

// ------------------ final loss reduce ------------------
__global__ __launch_bounds__(256) void k_loss(float* __restrict__ dout) {
    __shared__ float s1[256];
    __shared__ float s2[256];
    int tid = threadIdx.x;
    float a = 0.0f, b = 0.0f;
    for (int i = tid; i < NTOK; i += 256) { a += g_nllw[i]; b += g_wtok[i]; }
    s1[tid] = a; s2[tid] = b;
    __syncthreads();
    for (int off = 128; off; off >>= 1) {
        if (tid < off) { s1[tid] += s1[tid + off]; s2[tid] += s2[tid + off]; }
        __syncthreads();
    }
    if (tid == 0) dout[0] = s1[0] / s2[0];
}

// ------------------ launch ------------------
extern "C" void kernel_launch(void* const* d_in, const int* in_sizes, int n_in,
                              void* d_out, int out_size) {
    const int* inp_word = (const int*)d_in[0];
    const float* inp_mask = (const float*)d_in[1];
    const int* tgt_word = (const int*)d_in[3];
    const float* emb = (const float*)d_in[4];
    const float* w_ih0 = (const float*)d_in[5];
    const float* w_hh0 = (const float*)d_in[6];
    const float* b0 = (const float*)d_in[7];
    const float* w_ih = (const float*)d_in[8];
    const float* w_hh = (const float*)d_in[9];
    const float* bb = (const float*)d_in[10];
    const float* dec_w1 = (const float*)d_in[11];
    const float* dec_b1 = (const float*)d_in[12];
    const float* dec_w2 = (const float*)d_in[13];
    const float* dec_b2 = (const float*)d_in[14];
    const float* cew = (const float*)d_in[15];
    float* out = (float*)d_out;

    float *pgx, *phid, *pwh, *pwl, *pah, *pal, *pwhh, *pwhl;
    cudaGetSymbolAddress((void**)&pgx, g_gx);
    cudaGetSymbolAddress((void**)&phid, g_hid);
    cudaGetSymbolAddress((void**)&pwh, g_wh);
    cudaGetSymbolAddress((void**)&pwl, g_wl);
    cudaGetSymbolAddress((void**)&pah, g_ah);
    cudaGetSymbolAddress((void**)&pal, g_al);
    cudaGetSymbolAddress((void**)&pwhh, g_whhh);
    cudaGetSymbolAddress((void**)&pwhl, g_whhl);

    const int gsm = 2 * STAGE * 4;                 // 81920 bytes
    const int ssm = (2 * 16896 + 2 * 4224) * 4;    // 168960 bytes
    cudaFuncSetAttribute(k_gemm2, cudaFuncAttributeMaxDynamicSharedMemorySize, gsm);
    cudaFuncSetAttribute(k_dec2m, cudaFuncAttributeMaxDynamicSharedMemorySize, gsm);
    cudaFuncSetAttribute(k_scan4, cudaFuncAttributeMaxDynamicSharedMemorySize, ssm);

    // 0. split all weights into tf32 hi/lo planes (once)
    k_split<<<512, 256>>>(w_ih0, pwh + OFF_WIH0, pwl + OFF_WIH0, 524288 / 4);
    k_split<<<8192, 256>>>(w_ih, pwh + OFF_WIH1, pwl + OFF_WIH1, 8388608 / 4);
    k_split<<<128, 256>>>(dec_w1, pwh + OFF_W1, pwl + OFF_W1, 131072 / 4);
    k_split<<<4000, 256>>>(dec_w2, pwh + OFF_W2, pwl + OFF_W2, 4096000 / 4);
    k_split<<<2048, 256>>>(w_hh0, pwhh, pwhl, 2097152 / 4);
    k_split<<<4096, 256>>>(w_hh, pwhh + 2097152, pwhl + 2097152, 4194304 / 4);

    // 1. embedding (split planes, K=128)
    k_embed<<<(NTOK * NE) / 256, 256>>>(inp_word, emb);

    // 2. layer 0
    k_gemm2<<<dim3(NG / 128, NTOK / 128, 2), 256, gsm>>>(
        pah, pal, pwh + OFF_WIH0, pwl + OFF_WIH0, b0, pgx,
        NE, NG, (long long)NG * NE, NG, (long long)NTOK * NG, 0);
    k_zero<<<128, 256>>>();
    k_scan4<<<128, 256, ssm>>>(pgx, inp_mask, pwhh, pwhl);

    // 3. layer 1 (scan wrote split activations directly)
    k_gemm2<<<dim3(NG / 128, NTOK / 128, 2), 256, gsm>>>(
        pah, pal, pwh + OFF_WIH1, pwl + OFF_WIH1, bb, pgx,
        1024, NG, (long long)NG * 1024, NG, (long long)NTOK * NG, 0);
    k_zero<<<128, 256>>>();
    k_scan4<<<128, 256, ssm>>>(pgx, inp_mask, pwhh + 2097152, pwhl + 2097152);

    // 4. layer 2
    k_gemm2<<<dim3(NG / 128, NTOK / 128, 2), 256, gsm>>>(
        pah, pal, pwh + OFF_WIH1 + 4194304, pwl + OFF_WIH1 + 4194304,
        bb + 2 * NG, pgx,
        1024, NG, (long long)NG * 1024, NG, (long long)NTOK * NG, 0);
    k_zero<<<128, 256>>>();
    k_scan4<<<128, 256, ssm>>>(pgx, inp_mask, pwhh + 4194304, pwhl + 4194304);

    // 5. decoder layer 1 (relu, writes g_hid + split planes)
    k_gemm2<<<dim3(1, NTOK / 128, 1), 256, gsm>>>(
        pah, pal, pwh + OFF_W1, pwl + OFF_W1, dec_b1, phid,
        1024, 128, 0, 0, 0, 2);

    // 6. decoder layer 2 (mma) + fused online softmax partials
    k_dec2m<<<dim3(NVT, NTOK / 128), 256, gsm>>>(dec_b2);

    // 7. per-token combine
    k_comb<<<NTOK / 8, 256>>>(dec_w2, dec_b2, tgt_word, cew, out);

    // 8. loss reduce
    k_loss<<<1, 256>>>(out);
}

// round 11
// speedup vs baseline: 1.0338x; 1.0046x over previous
#include <cuda_runtime.h>
#include <math.h>
#include <stdint.h>

#define NB 32
#define NL 128
#define NH 512
#define NG 2048
#define NV 32000
#define NE 128
#define NTOK 4096
#define NVT 250

// weight-plane arena offsets (floats)
#define OFF_WIH0 0
#define OFF_WIH1 524288
#define OFF_W1   8912896
#define OFF_W2   9043968
#define WARENA   13139968

// ------------------ scratch ------------------
__device__ float g_wh[WARENA];
__device__ float g_wl[WARENA];
__device__ float g_whhh[3 * 2 * NG * NH];
__device__ float g_whhl[3 * 2 * NG * NH];
__device__ float g_ah[NTOK * 1024];
__device__ float g_al[NTOK * 1024];
__device__ float g_gx[2u * NTOK * NG];          // [d][t][g][b] (transposed!)
__device__ float g_hid[NTOK * 128];
__device__ float g_hidh[NTOK * 128];
__device__ float g_hidl[NTOK * 128];
__device__ float g_hph[2 * NB * NH];
__device__ float g_hpl[2 * NB * NH];
__device__ float g_part[2 * 4 * NG * NB];       // [dir][ks][g][b]
__device__ float g_maskt[NL * NB];              // [t][b]
__device__ float g_pmax[(size_t)NTOK * NVT];
__device__ float g_psum[(size_t)NTOK * NVT];
__device__ int   g_parg[(size_t)NTOK * NVT];
__device__ float g_nllw[NTOK];
__device__ float g_wtok[NTOK];
__device__ unsigned int g_barcnt2[2];

// ------------------ helpers ------------------
__device__ __forceinline__ float sigf(float x) {
    return 1.0f / (1.0f + __expf(-x));
}
__device__ __forceinline__ float tanhf_fast(float x) {
    float e = __expf(-2.0f * fabsf(x));
    float r = (1.0f - e) / (1.0f + e);
    return copysignf(r, x);
}

// per-direction grid barrier over 64 blocks: release/acquire
__device__ __forceinline__ void gridbar_d(int d) {
    __syncthreads();
    if (threadIdx.x == 0) {
        unsigned int* ctr = &g_barcnt2[d];
        unsigned int t;
        asm volatile("atom.add.release.gpu.u32 %0, [%1], 1;"
                     : "=r"(t) : "l"(ctr) : "memory");
        unsigned int need = ((t >> 6) + 1u) << 6;
        unsigned int cur;
        do {
            asm volatile("ld.acquire.gpu.u32 %0, [%1];"
                         : "=r"(cur) : "l"(ctr) : "memory");
        } while (cur < need);
    }
    __syncthreads();
}

__device__ __forceinline__ void tf32split(float x, float& hi, float& lo) {
    unsigned hb;
    asm("cvt.rna.tf32.f32 %0, %1;" : "=r"(hb) : "f"(x));
    float hf = __uint_as_float(hb);
    float l = x - hf;
    unsigned lb;
    asm("cvt.rna.tf32.f32 %0, %1;" : "=r"(lb) : "f"(l));
    hi = hf;
    lo = __uint_as_float(lb);
}

#define MMA_TF32(c, a, b)                                                     \
    asm volatile(                                                             \
        "mma.sync.aligned.m16n8k8.row.col.f32.tf32.tf32.f32 "                 \
        "{%0,%1,%2,%3}, {%4,%5,%6,%7}, {%8,%9}, {%0,%1,%2,%3};"               \
        : "+f"((c)[0]), "+f"((c)[1]), "+f"((c)[2]), "+f"((c)[3])              \
        : "r"((a)[0]), "r"((a)[1]), "r"((a)[2]), "r"((a)[3]),                 \
          "r"((b)[0]), "r"((b)[1]))

__device__ __forceinline__ void cp16(uint32_t dst, const float* src) {
    asm volatile("cp.async.cg.shared.global [%0], [%1], 16;" :: "r"(dst), "l"(src));
}
#define CP_COMMIT() asm volatile("cp.async.commit_group;")
#define CP_WAIT1()  asm volatile("cp.async.wait_group 1;")
#define CP_WAIT0()  asm volatile("cp.async.wait_group 0;")

// gemm stage layout: 4 planes (AH, AL, BH, BL) x 128 rows x 20 floats
#define PLANE 2560
#define STAGE 10240

// ------------------ split kernel (weights only) ------------------
__global__ __launch_bounds__(256) void k_split(const float* __restrict__ s,
                                               float* __restrict__ dh,
                                               float* __restrict__ dl, int n4) {
    int i = blockIdx.x * 256 + threadIdx.x;
    if (i < n4) {
        float4 v = ((const float4*)s)[i];
        float4 h4, l4;
        tf32split(v.x, h4.x, l4.x);
        tf32split(v.y, h4.y, l4.y);
        tf32split(v.z, h4.z, l4.z);
        tf32split(v.w, h4.w, l4.w);
        ((float4*)dh)[i] = h4;
        ((float4*)dl)[i] = l4;
    }
}

// ------------------ embedding (writes split planes) ------------------
__global__ __launch_bounds__(256) void k_embed(const int* __restrict__ w,
                                               const float* __restrict__ emb) {
    int i = blockIdx.x * 256 + threadIdx.x;
    float v = emb[(size_t)w[i >> 7] * NE + (i & 127)];
    float h, l;
    tf32split(v, h, l);
    g_ah[i] = h;
    g_al[i] = l;
}

// ------------------ mask transpose ------------------
__global__ __launch_bounds__(256) void k_maskt(const float* __restrict__ mask) {
    int i = blockIdx.x * 256 + threadIdx.x;   // 0..4095
    int t = i >> 5, b = i & 31;
    g_maskt[i] = mask[b * NL + t];
}

// ------------------ zero h planes + barrier counters ------------------
__global__ __launch_bounds__(256) void k_zero() {
    int i = blockIdx.x * 256 + threadIdx.x;
    if (i < 2 * NB * NH) { g_hph[i] = 0.0f; g_hpl[i] = 0.0f; }
    if (i < 2) g_barcnt2[i] = 0u;
}

// ------------------ 3xTF32 mma GEMM, presplit inputs, cp.async pipeline ----
// gxt=1: write C transposed as [t][n][b] (per dir), b = m>>7, t = m&127.
__global__ __launch_bounds__(256) void k_gemm2(const float* __restrict__ Ahp,
                                               const float* __restrict__ Alp,
                                               const float* __restrict__ Whp,
                                               const float* __restrict__ Wlp,
                                               const float* __restrict__ bias,
                                               float* __restrict__ C,
                                               int K, int N,
                                               long long wStr, long long bStr,
                                               long long cStr, int mode, int gxt) {
    extern __shared__ float smf[];
    uint32_t smb = (uint32_t)__cvta_generic_to_shared(smf);

    int d = blockIdx.z;
    Whp += (size_t)d * wStr;
    Wlp += (size_t)d * wStr;
    bias += (size_t)d * bStr;
    C += (size_t)d * cStr;

    int tid = threadIdx.x;
    int m0 = blockIdx.y << 7, n0 = blockIdx.x << 7;
    int lr = tid >> 2, lkq = (tid & 3) << 2;

    const float* pA0h = Ahp + (size_t)(m0 + lr) * K + lkq;
    const float* pA1h = Ahp + (size_t)(m0 + lr + 64) * K + lkq;
    const float* pA0l = Alp + (size_t)(m0 + lr) * K + lkq;
    const float* pA1l = Alp + (size_t)(m0 + lr + 64) * K + lkq;
    const float* pB0h = Whp + (size_t)(n0 + lr) * K + lkq;
    const float* pB1h = Whp + (size_t)(n0 + lr + 64) * K + lkq;
    const float* pB0l = Wlp + (size_t)(n0 + lr) * K + lkq;
    const float* pB1l = Wlp + (size_t)(n0 + lr + 64) * K + lkq;

    uint32_t o0 = (uint32_t)((0 * PLANE + lr * 20 + lkq) * 4);
    uint32_t o1 = (uint32_t)((0 * PLANE + (lr + 64) * 20 + lkq) * 4);
    uint32_t o2 = (uint32_t)((1 * PLANE + lr * 20 + lkq) * 4);
    uint32_t o3 = (uint32_t)((1 * PLANE + (lr + 64) * 20 + lkq) * 4);
    uint32_t o4 = (uint32_t)((2 * PLANE + lr * 20 + lkq) * 4);
    uint32_t o5 = (uint32_t)((2 * PLANE + (lr + 64) * 20 + lkq) * 4);
    uint32_t o6 = (uint32_t)((3 * PLANE + lr * 20 + lkq) * 4);
    uint32_t o7 = (uint32_t)((3 * PLANE + (lr + 64) * 20 + lkq) * 4);

    int wid = tid >> 5, lane = tid & 31;
    int gid = lane >> 2, t4 = lane & 3;
    int wm = (wid >> 2) << 6;
    int wn = (wid & 3) << 5;

    float acc[4][4][4];
#pragma unroll
    for (int mt = 0; mt < 4; mt++)
#pragma unroll
        for (int nt = 0; nt < 4; nt++)
#pragma unroll
            for (int r = 0; r < 4; r++) acc[mt][nt][r] = 0.0f;

    int T = K >> 4;
    {
        uint32_t b = smb;
        cp16(b + o0, pA0h); cp16(b + o1, pA1h);
        cp16(b + o2, pA0l); cp16(b + o3, pA1l);
        cp16(b + o4, pB0h); cp16(b + o5, pB1h);
        cp16(b + o6, pB0l); cp16(b + o7, pB1l);
        CP_COMMIT();
    }

    for (int kt = 0; kt < T; kt++) {
        int s = kt & 1;
        if (kt + 1 < T) {
            int ko = (kt + 1) << 4;
            uint32_t b = smb + (uint32_t)((s ^ 1) * STAGE * 4);
            cp16(b + o0, pA0h + ko); cp16(b + o1, pA1h + ko);
            cp16(b + o2, pA0l + ko); cp16(b + o3, pA1l + ko);
            cp16(b + o4, pB0h + ko); cp16(b + o5, pB1h + ko);
            cp16(b + o6, pB0l + ko); cp16(b + o7, pB1l + ko);
            CP_COMMIT();
            CP_WAIT1();
        } else {
            CP_WAIT0();
        }
        __syncthreads();
        const float* S = smf + s * STAGE;

#pragma unroll
        for (int k8 = 0; k8 < 16; k8 += 8) {
            unsigned ah[4][4], al[4][4];
#pragma unroll
            for (int mt = 0; mt < 4; mt++) {
                int r0i = (wm + (mt << 4) + gid) * 20 + k8 + t4;
                int r1i = (wm + (mt << 4) + gid + 8) * 20 + k8 + t4;
                ah[mt][0] = __float_as_uint(S[r0i]);
                ah[mt][1] = __float_as_uint(S[r1i]);
                ah[mt][2] = __float_as_uint(S[r0i + 4]);
                ah[mt][3] = __float_as_uint(S[r1i + 4]);
                al[mt][0] = __float_as_uint(S[PLANE + r0i]);
                al[mt][1] = __float_as_uint(S[PLANE + r1i]);
                al[mt][2] = __float_as_uint(S[PLANE + r0i + 4]);
                al[mt][3] = __float_as_uint(S[PLANE + r1i + 4]);
            }
            unsigned bh[4][2], bl[4][2];
#pragma unroll
            for (int nt = 0; nt < 4; nt++) {
                int ci = (wn + (nt << 3) + gid) * 20 + k8 + t4;
                bh[nt][0] = __float_as_uint(S[2 * PLANE + ci]);
                bh[nt][1] = __float_as_uint(S[2 * PLANE + ci + 4]);
                bl[nt][0] = __float_as_uint(S[3 * PLANE + ci]);
                bl[nt][1] = __float_as_uint(S[3 * PLANE + ci + 4]);
            }
#pragma unroll
            for (int mt = 0; mt < 4; mt++)
#pragma unroll
                for (int nt = 0; nt < 4; nt++) {
                    MMA_TF32(acc[mt][nt], ah[mt], bh[nt]);
                    MMA_TF32(acc[mt][nt], ah[mt], bl[nt]);
                    MMA_TF32(acc[mt][nt], al[mt], bh[nt]);
                }
        }
        __syncthreads();
    }

#pragma unroll
    for (int mt = 0; mt < 4; mt++) {
#pragma unroll
        for (int nt = 0; nt < 4; nt++) {
            int m = m0 + wm + (mt << 4) + gid;
            int n = n0 + wn + (nt << 3) + (t4 << 1);
            float bv0 = bias[n], bv1 = bias[n + 1];
            float v0 = acc[mt][nt][0] + bv0;
            float v1 = acc[mt][nt][1] + bv1;
            float v2 = acc[mt][nt][2] + bv0;
            float v3 = acc[mt][nt][3] + bv1;
            if (mode) {
                v0 = fmaxf(v0, 0.0f); v1 = fmaxf(v1, 0.0f);
                v2 = fmaxf(v2, 0.0f); v3 = fmaxf(v3, 0.0f);
            }
            if (gxt) {
                // transposed gx: [t][n][b], b = m>>7, t = m&127
                int b = m >> 7;
                int tt = m & 127;
                C[((size_t)tt * NG + n) * NB + b] = v0;
                C[((size_t)tt * NG + n + 1) * NB + b] = v1;
                C[((size_t)(tt + 8) * NG + n) * NB + b] = v2;
                C[((size_t)(tt + 8) * NG + n + 1) * NB + b] = v3;
            } else {
                float2 p0 = {v0, v1};
                float2 p1 = {v2, v3};
                *(float2*)(C + (size_t)m * N + n) = p0;
                *(float2*)(C + (size_t)(m + 8) * N + n) = p1;
                if (mode == 2) {
                    float h, l;
                    size_t i0 = (size_t)m * N + n;
                    size_t i1 = (size_t)(m + 8) * N + n;
                    tf32split(v0, h, l); g_hidh[i0] = h;     g_hidl[i0] = l;
                    tf32split(v1, h, l); g_hidh[i0 + 1] = h; g_hidl[i0 + 1] = l;
                    tf32split(v2, h, l); g_hidh[i1] = h;     g_hidl[i1] = l;
                    tf32split(v3, h, l); g_hidh[i1 + 1] = h; g_hidl[i1 + 1] = l;
                }
            }
        }
    }
}

// ------------------ decoder2 mma: logits tile + online softmax partials ----
__global__ __launch_bounds__(256) void k_dec2m(const float* __restrict__ b2) {
    extern __shared__ float smf[];
    uint32_t smb = (uint32_t)__cvta_generic_to_shared(smf);
    __shared__ float wmax[256];
    __shared__ int   warg[256];
    __shared__ float wsum[256];
    __shared__ float bmx[128];

    const float* Ahp = g_wh + OFF_W2;
    const float* Alp = g_wl + OFF_W2;

    int tid = threadIdx.x;
    int vt = blockIdx.x;
    int v0 = vt << 7;
    int n0 = blockIdx.y << 7;
    int lr = tid >> 2, lkq = (tid & 3) << 2;
    const int K = 128;

    const float* pA0h = Ahp + (size_t)(v0 + lr) * K + lkq;
    const float* pA1h = Ahp + (size_t)(v0 + lr + 64) * K + lkq;
    const float* pA0l = Alp + (size_t)(v0 + lr) * K + lkq;
    const float* pA1l = Alp + (size_t)(v0 + lr + 64) * K + lkq;
    const float* pB0h = g_hidh + (size_t)(n0 + lr) * K + lkq;
    const float* pB1h = g_hidh + (size_t)(n0 + lr + 64) * K + lkq;
    const float* pB0l = g_hidl + (size_t)(n0 + lr) * K + lkq;
    const float* pB1l = g_hidl + (size_t)(n0 + lr + 64) * K + lkq;

    uint32_t o0 = (uint32_t)((0 * PLANE + lr * 20 + lkq) * 4);
    uint32_t o1 = (uint32_t)((0 * PLANE + (lr + 64) * 20 + lkq) * 4);
    uint32_t o2 = (uint32_t)((1 * PLANE + lr * 20 + lkq) * 4);
    uint32_t o3 = (uint32_t)((1 * PLANE + (lr + 64) * 20 + lkq) * 4);
    uint32_t o4 = (uint32_t)((2 * PLANE + lr * 20 + lkq) * 4);
    uint32_t o5 = (uint32_t)((2 * PLANE + (lr + 64) * 20 + lkq) * 4);
    uint32_t o6 = (uint32_t)((3 * PLANE + lr * 20 + lkq) * 4);
    uint32_t o7 = (uint32_t)((3 * PLANE + (lr + 64) * 20 + lkq) * 4);

    int wid = tid >> 5, lane = tid & 31;
    int gid = lane >> 2, t4 = lane & 3;
    int wm = (wid >> 2) << 6;
    int wn = (wid & 3) << 5;

    float acc[4][4][4];
#pragma unroll
    for (int mt = 0; mt < 4; mt++)
#pragma unroll
        for (int nt = 0; nt < 4; nt++)
#pragma unroll
            for (int r = 0; r < 4; r++) acc[mt][nt][r] = 0.0f;

    const int T = 8;
    {
        uint32_t b = smb;
        cp16(b + o0, pA0h); cp16(b + o1, pA1h);
        cp16(b + o2, pA0l); cp16(b + o3, pA1l);
        cp16(b + o4, pB0h); cp16(b + o5, pB1h);
        cp16(b + o6, pB0l); cp16(b + o7, pB1l);
        CP_COMMIT();
    }
    for (int kt = 0; kt < T; kt++) {
        int s = kt & 1;
        if (kt + 1 < T) {
            int ko = (kt + 1) << 4;
            uint32_t b = smb + (uint32_t)((s ^ 1) * STAGE * 4);
            cp16(b + o0, pA0h + ko); cp16(b + o1, pA1h + ko);
            cp16(b + o2, pA0l + ko); cp16(b + o3, pA1l + ko);
            cp16(b + o4, pB0h + ko); cp16(b + o5, pB1h + ko);
            cp16(b + o6, pB0l + ko); cp16(b + o7, pB1l + ko);
            CP_COMMIT();
            CP_WAIT1();
        } else {
            CP_WAIT0();
        }
        __syncthreads();
        const float* S = smf + s * STAGE;
#pragma unroll
        for (int k8 = 0; k8 < 16; k8 += 8) {
            unsigned ah[4][4], al[4][4];
#pragma unroll
            for (int mt = 0; mt < 4; mt++) {
                int r0i = (wm + (mt << 4) + gid) * 20 + k8 + t4;
                int r1i = (wm + (mt << 4) + gid + 8) * 20 + k8 + t4;
                ah[mt][0] = __float_as_uint(S[r0i]);
                ah[mt][1] = __float_as_uint(S[r1i]);
                ah[mt][2] = __float_as_uint(S[r0i + 4]);
                ah[mt][3] = __float_as_uint(S[r1i + 4]);
                al[mt][0] = __float_as_uint(S[PLANE + r0i]);
                al[mt][1] = __float_as_uint(S[PLANE + r1i]);
                al[mt][2] = __float_as_uint(S[PLANE + r0i + 4]);
                al[mt][3] = __float_as_uint(S[PLANE + r1i + 4]);
            }
            unsigned bh[4][2], bl[4][2];
#pragma unroll
            for (int nt = 0; nt < 4; nt++) {
                int ci = (wn + (nt << 3) + gid) * 20 + k8 + t4;
                bh[nt][0] = __float_as_uint(S[2 * PLANE + ci]);
                bh[nt][1] = __float_as_uint(S[2 * PLANE + ci + 4]);
                bl[nt][0] = __float_as_uint(S[3 * PLANE + ci]);
                bl[nt][1] = __float_as_uint(S[3 * PLANE + ci + 4]);
            }
#pragma unroll
            for (int mt = 0; mt < 4; mt++)
#pragma unroll
                for (int nt = 0; nt < 4; nt++) {
                    MMA_TF32(acc[mt][nt], ah[mt], bh[nt]);
                    MMA_TF32(acc[mt][nt], ah[mt], bl[nt]);
                    MMA_TF32(acc[mt][nt], al[mt], bh[nt]);
                }
        }
        __syncthreads();
    }

    float bvv[4][2];
#pragma unroll
    for (int mt = 0; mt < 4; mt++) {
        bvv[mt][0] = b2[v0 + wm + (mt << 4) + gid];
        bvv[mt][1] = b2[v0 + wm + (mt << 4) + gid + 8];
    }
#pragma unroll
    for (int mt = 0; mt < 4; mt++)
#pragma unroll
        for (int nt = 0; nt < 4; nt++) {
            acc[mt][nt][0] += bvv[mt][0];
            acc[mt][nt][1] += bvv[mt][0];
            acc[mt][nt][2] += bvv[mt][1];
            acc[mt][nt][3] += bvv[mt][1];
        }

#pragma unroll
    for (int nt = 0; nt < 4; nt++) {
#pragma unroll
        for (int c = 0; c < 2; c++) {
            float lm = -1e30f;
            int la = 0;
#pragma unroll
            for (int mt = 0; mt < 4; mt++)
#pragma unroll
                for (int ro = 0; ro < 2; ro++) {
                    float lg = acc[mt][nt][ro * 2 + c];
                    if (lg > lm) {
                        lm = lg;
                        la = v0 + wm + (mt << 4) + gid + ro * 8;
                    }
                }
#pragma unroll
            for (int off = 4; off <= 16; off <<= 1) {
                float om = __shfl_xor_sync(0xffffffffu, lm, off);
                int oa = __shfl_xor_sync(0xffffffffu, la, off);
                if (om > lm || (om == lm && oa < la)) { lm = om; la = oa; }
            }
            if (gid == 0) {
                int tcol = wn + (nt << 3) + (t4 << 1) + c;
                wmax[(wm >> 6) * 128 + tcol] = lm;
                warg[(wm >> 6) * 128 + tcol] = la;
            }
        }
    }
    __syncthreads();
    float fm = 0.0f;
    int fa = 0;
    if (tid < 128) {
        float ma = wmax[tid], mb = wmax[128 + tid];
        if (mb > ma) { fm = mb; fa = warg[128 + tid]; }
        else { fm = ma; fa = warg[tid]; }
        bmx[tid] = fm;
    }
    __syncthreads();

#pragma unroll
    for (int nt = 0; nt < 4; nt++) {
#pragma unroll
        for (int c = 0; c < 2; c++) {
            int tcol = wn + (nt << 3) + (t4 << 1) + c;
            float mx = bmx[tcol];
            float s = 0.0f;
#pragma unroll
            for (int mt = 0; mt < 4; mt++)
#pragma unroll
                for (int ro = 0; ro < 2; ro++)
                    s += __expf(acc[mt][nt][ro * 2 + c] - mx);
#pragma unroll
            for (int off = 4; off <= 16; off <<= 1)
                s += __shfl_xor_sync(0xffffffffu, s, off);
            if (gid == 0) wsum[(wm >> 6) * 128 + tcol] = s;
        }
    }
    __syncthreads();
    if (tid < 128) {
        size_t tok = (size_t)(n0 + tid);
        g_pmax[tok * NVT + vt] = fm;
        g_parg[tok * NVT + vt] = fa;
        g_psum[tok * NVT + vt] = wsum[tid] + wsum[128 + tid];
    }
}

// ------------------ persistent BiLSTM scan v4.2 (coalesced combine) --------
__global__ __launch_bounds__(256) void k_scan4(const float* __restrict__ gx,
                                               const float* __restrict__ whh_h,
                                               const float* __restrict__ whh_l) {
    extern __shared__ float sm[];
    float* Wh = sm;                         // [128][132]
    float* Wl = sm + 16896;                 // [128][132]
    float* Hh = sm + 33792;                 // [32][132]
    float* Hl = sm + 33792 + 4224;          // [32][132]
    uint32_t smb = (uint32_t)__cvta_generic_to_shared(sm);

    int tid = threadIdx.x;
    int bid = blockIdx.x;
    int d = bid >> 6;
    int ks = (bid >> 4) & 3;
    int gt = bid & 15;
    int g0 = gt << 7;
    int k0 = ks << 7;

    // preload Whh hi/lo tile (once per layer)
#pragma unroll
    for (int p = 0; p < 2; p++) {
        const float* src = p ? whh_l : whh_h;
        float* dst = p ? Wl : Wh;
#pragma unroll
        for (int j = 0; j < 16; j++) {
            int idx = tid + j * 256;
            int row = idx >> 5;
            int c = (idx & 31) << 2;
            float4 v = __ldg((const float4*)(src + (size_t)(d * NG + g0 + row) * NH + k0 + c));
            *(float4*)&dst[row * 132 + c] = v;
        }
    }

    int wid = tid >> 5, lane = tid & 31;
    int gid = lane >> 2, t4 = lane & 3;
    int rowbase = wid << 4;

    // combine role
    int jt = bid & 63;
    int cb = tid & 31;
    int jl = tid >> 5;
    int cj = (jt << 3) + jl;
    float creg = 0.0f, hreg = 0.0f;

    const float* gxd = gx + (size_t)d * NL * NG * NB;

    __syncthreads();

    for (int s = 0; s < NL; s++) {
        int t = d ? (NL - 1 - s) : s;

        // ---- prefetch gx + mask (coalesced, independent of partials) ----
        float gin[4];
        {
            const float* gxr = gxd + (size_t)t * NG * NB + cb;
#pragma unroll
            for (int gi = 0; gi < 4; gi++)
                gin[gi] = __ldg(&gxr[(size_t)(gi * NH + cj) * NB]);
        }
        float mt = g_maskt[t * NB + cb];

        // ---- stage h planes via cp.async ----
        {
            int idx = tid;
#pragma unroll
            for (int j = 0; j < 8; j++, idx += 256) {
                int p = idx >> 10;
                int rem = idx & 1023;
                int row = rem >> 5;
                int c = (rem & 31) << 2;
                const float* src = (p ? g_hpl : g_hph) + (size_t)(d * NB + row) * NH + k0 + c;
                uint32_t dst = smb + (uint32_t)(((p ? 38016 : 33792) + row * 132 + c) * 4);
                cp16(dst, src);
            }
            CP_COMMIT();
            CP_WAIT0();
        }
        __syncthreads();

        // ---- mma partial: [128 gates] x [32 b] over k-slice ----
        float acc[4][4];
#pragma unroll
        for (int nt = 0; nt < 4; nt++)
#pragma unroll
            for (int r = 0; r < 4; r++) acc[nt][r] = 0.0f;

#pragma unroll
        for (int k8 = 0; k8 < 16; k8++) {
            int kk = (k8 << 3) + t4;
            int r0 = (rowbase + gid) * 132 + kk;
            int r1 = r0 + 8 * 132;
            unsigned ah[4], al[4];
            ah[0] = __float_as_uint(Wh[r0]);
            ah[1] = __float_as_uint(Wh[r1]);
            ah[2] = __float_as_uint(Wh[r0 + 4]);
            ah[3] = __float_as_uint(Wh[r1 + 4]);
            al[0] = __float_as_uint(Wl[r0]);
            al[1] = __float_as_uint(Wl[r1]);
            al[2] = __float_as_uint(Wl[r0 + 4]);
            al[3] = __float_as_uint(Wl[r1 + 4]);
#pragma unroll
            for (int nt = 0; nt < 4; nt++) {
                int ci = ((nt << 3) + gid) * 132 + kk;
                unsigned bh[2], bl[2];
                bh[0] = __float_as_uint(Hh[ci]);
                bh[1] = __float_as_uint(Hh[ci + 4]);
                bl[0] = __float_as_uint(Hl[ci]);
                bl[1] = __float_as_uint(Hl[ci + 4]);
                MMA_TF32(acc[nt], ah, bh);
                MMA_TF32(acc[nt], ah, bl);
                MMA_TF32(acc[nt], al, bh);
            }
        }

        // ---- store partials ----
        {
            size_t pbase = ((size_t)(d * 4 + ks) * NG + g0) * NB;
            int grow = rowbase + gid;
#pragma unroll
            for (int nt = 0; nt < 4; nt++) {
                int b = (nt << 3) + (t4 << 1);
                float2 p0 = {acc[nt][0], acc[nt][1]};
                float2 p1 = {acc[nt][2], acc[nt][3]};
                *(float2*)&g_part[pbase + (size_t)grow * NB + b] = p0;
                *(float2*)&g_part[pbase + (size_t)(grow + 8) * NB + b] = p1;
            }
        }
        gridbar_d(d);

        // ---- combine: one (b, j) per thread ----
        {
            float gate[4];
#pragma unroll
            for (int gi = 0; gi < 4; gi++) {
                int g = gi * NH + cj;
                float v = gin[gi];
#pragma unroll
                for (int kss = 0; kss < 4; kss++)
                    v += __ldcg(&g_part[((size_t)(d * 4 + kss) * NG + g) * NB + cb]);
                gate[gi] = v;
            }
            float cn = sigf(gate[1]) * creg + sigf(gate[0]) * tanhf_fast(gate[2]);
            float hn = sigf(gate[3]) * tanhf_fast(cn);
            hreg = hreg + (hn - hreg) * mt;
            creg = creg + (cn - creg) * mt;
            float hh, hl;
            tf32split(hreg, hh, hl);
            size_t hidx = (size_t)(d * NB + cb) * NH + cj;
            g_hph[hidx] = hh;
            g_hpl[hidx] = hl;
            // fused split sequence output (next layer's A planes)
            size_t oidx = ((size_t)cb * NL + t) * 1024 + (d << 9) + cj;
            g_ah[oidx] = hh;
            g_al[oidx] = hl;
        }
        gridbar_d(d);
    }
}

// ------------------ per-token combine ------------------
__global__ __launch_bounds__(256) void k_comb(const float* __restrict__ w2,
                                              const float* __restrict__ b2,
                                              const int* __restrict__ tgt,
                                              const float* __restrict__ cew,
                                              float* __restrict__ dout) {
    int warp = threadIdx.x >> 5, lane = threadIdx.x & 31;
    int m = blockIdx.x * 8 + warp;

    float lm = -1e30f, ls = 0.0f;
    int la = 0;
    for (int vt = lane; vt < NVT; vt += 32) {
        float tmx = g_pmax[(size_t)m * NVT + vt];
        float tsm = g_psum[(size_t)m * NVT + vt];
        int tag = g_parg[(size_t)m * NVT + vt];
        if (tmx > lm) {
            ls = ls * __expf(lm - tmx) + tsm;
            lm = tmx;
            la = tag;
        } else {
            ls += tsm * __expf(tmx - lm);
        }
    }
#pragma unroll
    for (int off = 16; off; off >>= 1) {
        float om = __shfl_down_sync(0xffffffffu, lm, off);
        float os = __shfl_down_sync(0xffffffffu, ls, off);
        int oa = __shfl_down_sync(0xffffffffu, la, off);
        float nm = fmaxf(lm, om);
        float ns = ls * __expf(lm - nm) + os * __expf(om - nm);
        int na = (om > lm) ? oa : ((om == lm && oa < la) ? oa : la);
        lm = nm; ls = ns; la = na;
    }

    int tg = tgt[m];
    float4 hv = *(const float4*)&g_hid[(size_t)m * 128 + lane * 4];
    float4 wv = *(const float4*)&w2[(size_t)tg * 128 + lane * 4];
    float dp = hv.x * wv.x + hv.y * wv.y + hv.z * wv.z + hv.w * wv.w;
#pragma unroll
    for (int off = 16; off; off >>= 1) dp += __shfl_down_sync(0xffffffffu, dp, off);

    if (lane == 0) {
        float logit_t = dp + b2[tg];
        float lse = lm + logf(ls);
        float nll = lse - logit_t;
        float w = cew[tg];
        g_nllw[m] = nll * w;
        g_wtok[m] = w;
        dout[1 + m] = (float)la;
    }
}

// ------------------ final loss reduce ------------------
__global__ __launch_bounds__(256) void k_loss(float* __restrict__ dout) {
    __shared__ float s1[256];
    __shared__ float s2[256];
    int tid = threadIdx.x;
    float a = 0.0f, b = 0.0f;
    for (int i = tid; i < NTOK; i += 256) { a += g_nllw[i]; b += g_wtok[i]; }
    s1[tid] = a; s2[tid] = b;
    __syncthreads();
    for (int off = 128; off; off >>= 1) {
        if (tid < off) { s1[tid] += s1[tid + off]; s2[tid] += s2[tid + off]; }
        __syncthreads();
    }
    if (tid == 0) dout[0] = s1[0] / s2[0];
}

// ------------------ launch ------------------
extern "C" void kernel_launch(void* const* d_in, const int* in_sizes, int n_in,
                              void* d_out, int out_size) {
    const int* inp_word = (const int*)d_in[0];
    const float* inp_mask = (const float*)d_in[1];
    const int* tgt_word = (const int*)d_in[3];
    const float* emb = (const float*)d_in[4];
    const float* w_ih0 = (const float*)d_in[5];
    const float* w_hh0 = (const float*)d_in[6];
    const float* b0 = (const float*)d_in[7];
    const float* w_ih = (const float*)d_in[8];
    const float* w_hh = (const float*)d_in[9];
    const float* bb = (const float*)d_in[10];
    const float* dec_w1 = (const float*)d_in[11];
    const float* dec_b1 = (const float*)d_in[12];
    const float* dec_w2 = (const float*)d_in[13];
    const float* dec_b2 = (const float*)d_in[14];
    const float* cew = (const float*)d_in[15];
    float* out = (float*)d_out;

    float *pgx, *phid, *pwh, *pwl, *pah, *pal, *pwhh, *pwhl;
    cudaGetSymbolAddress((void**)&pgx, g_gx);
    cudaGetSymbolAddress((void**)&phid, g_hid);
    cudaGetSymbolAddress((void**)&pwh, g_wh);
    cudaGetSymbolAddress((void**)&pwl, g_wl);
    cudaGetSymbolAddress((void**)&pah, g_ah);
    cudaGetSymbolAddress((void**)&pal, g_al);
    cudaGetSymbolAddress((void**)&pwhh, g_whhh);
    cudaGetSymbolAddress((void**)&pwhl, g_whhl);

    const int gsm = 2 * STAGE * 4;                 // 81920 bytes
    const int ssm = (2 * 16896 + 2 * 4224) * 4;    // 168960 bytes
    cudaFuncSetAttribute(k_gemm2, cudaFuncAttributeMaxDynamicSharedMemorySize, gsm);
    cudaFuncSetAttribute(k_dec2m, cudaFuncAttributeMaxDynamicSharedMemorySize, gsm);
    cudaFuncSetAttribute(k_scan4, cudaFuncAttributeMaxDynamicSharedMemorySize, ssm);

    // 0. split all weights into tf32 hi/lo planes + mask transpose
    k_split<<<512, 256>>>(w_ih0, pwh + OFF_WIH0, pwl + OFF_WIH0, 524288 / 4);
    k_split<<<8192, 256>>>(w_ih, pwh + OFF_WIH1, pwl + OFF_WIH1, 8388608 / 4);
    k_split<<<128, 256>>>(dec_w1, pwh + OFF_W1, pwl + OFF_W1, 131072 / 4);
    k_split<<<4000, 256>>>(dec_w2, pwh + OFF_W2, pwl + OFF_W2, 4096000 / 4);
    k_split<<<2048, 256>>>(w_hh0, pwhh, pwhl, 2097152 / 4);
    k_split<<<4096, 256>>>(w_hh, pwhh + 2097152, pwhl + 2097152, 4194304 / 4);
    k_maskt<<<16, 256>>>(inp_mask);

    // 1. embedding (split planes, K=128)
    k_embed<<<(NTOK * NE) / 256, 256>>>(inp_word, emb);

    // 2. layer 0
    k_gemm2<<<dim3(NG / 128, NTOK / 128, 2), 256, gsm>>>(
        pah, pal, pwh + OFF_WIH0, pwl + OFF_WIH0, b0, pgx,
        NE, NG, (long long)NG * NE, NG, (long long)NTOK * NG, 0, 1);
    k_zero<<<128, 256>>>();
    k_scan4<<<128, 256, ssm>>>(pgx, pwhh, pwhl);

    // 3. layer 1 (scan wrote split activations directly)
    k_gemm2<<<dim3(NG / 128, NTOK / 128, 2), 256, gsm>>>(
        pah, pal, pwh + OFF_WIH1, pwl + OFF_WIH1, bb, pgx,
        1024, NG, (long long)NG * 1024, NG, (long long)NTOK * NG, 0, 1);
    k_zero<<<128, 256>>>();
    k_scan4<<<128, 256, ssm>>>(pgx, pwhh + 2097152, pwhl + 2097152);

    // 4. layer 2
    k_gemm2<<<dim3(NG / 128, NTOK / 128, 2), 256, gsm>>>(
        pah, pal, pwh + OFF_WIH1 + 4194304, pwl + OFF_WIH1 + 4194304,
        bb + 2 * NG, pgx,
        1024, NG, (long long)NG * 1024, NG, (long long)NTOK * NG, 0, 1);
    k_zero<<<128, 256>>>();
    k_scan4<<<128, 256, ssm>>>(pgx, pwhh + 4194304, pwhl + 4194304);

    // 5. decoder layer 1 (relu, writes g_hid + split planes)
    k_gemm2<<<dim3(1, NTOK / 128, 1), 256, gsm>>>(
        pah, pal, pwh + OFF_W1, pwl + OFF_W1, dec_b1, phid,
        1024, 128, 0, 0, 0, 2, 0);

    // 6. decoder layer 2 (mma) + fused online softmax partials
    k_dec2m<<<dim3(NVT, NTOK / 128), 256, gsm>>>(dec_b2);

    // 7. per-token combine
    k_comb<<<NTOK / 8, 256>>>(dec_w2, dec_b2, tgt_word, cew, out);

    // 8. loss reduce
    k_loss<<<1, 256>>>(out);
}

// round 13
// speedup vs baseline: 1.1409x; 1.1036x over previous
#include <cuda_runtime.h>
#include <cuda_fp16.h>
#include <math.h>
#include <stdint.h>

#define NB 32
#define NL 128
#define NH 512
#define NG 2048
#define NV 32000
#define NE 128
#define NTOK 4096
#define NVT 250

// weight-plane arena offsets (floats)
#define OFF_WIH0 0
#define OFF_WIH1 524288
#define OFF_W1   8912896
#define OFF_W2   9043968
#define WARENA   13139968

// ------------------ scratch ------------------
__device__ float g_wh[WARENA];
__device__ float g_wl[WARENA];
__device__ __half g_whh16h[3 * 2 * NG * NH];
__device__ __half g_whh16l[3 * 2 * NG * NH];
__device__ float g_ah[NTOK * 1024];
__device__ float g_al[NTOK * 1024];
__device__ float g_gx[2u * NTOK * NG];          // [d][t][g][b]
__device__ float g_hid[NTOK * 128];
__device__ float g_hidh[NTOK * 128];
__device__ float g_hidl[NTOK * 128];
__device__ __half g_hph16[2 * NB * NH];
__device__ __half g_hpl16[2 * NB * NH];
__device__ float g_part[2 * 4 * NG * NB];
__device__ float g_maskt[NL * NB];
__device__ float g_pmax[(size_t)NTOK * NVT];
__device__ float g_psum[(size_t)NTOK * NVT];
__device__ int   g_parg[(size_t)NTOK * NVT];
__device__ float g_nllw[NTOK];
__device__ float g_wtok[NTOK];
__device__ unsigned int g_barcnt2[2];

// ------------------ helpers ------------------
__device__ __forceinline__ float sigf(float x) {
    return 1.0f / (1.0f + __expf(-x));
}
__device__ __forceinline__ float tanhf_fast(float x) {
    float e = __expf(-2.0f * fabsf(x));
    float r = (1.0f - e) / (1.0f + e);
    return copysignf(r, x);
}

__device__ __forceinline__ void gridbar_d(int d) {
    __syncthreads();
    if (threadIdx.x == 0) {
        unsigned int* ctr = &g_barcnt2[d];
        unsigned int t;
        asm volatile("atom.add.release.gpu.u32 %0, [%1], 1;"
                     : "=r"(t) : "l"(ctr) : "memory");
        unsigned int need = ((t >> 6) + 1u) << 6;
        unsigned int cur;
        do {
            asm volatile("ld.acquire.gpu.u32 %0, [%1];"
                         : "=r"(cur) : "l"(ctr) : "memory");
        } while (cur < need);
    }
    __syncthreads();
}

__device__ __forceinline__ void tf32split(float x, float& hi, float& lo) {
    unsigned hb;
    asm("cvt.rna.tf32.f32 %0, %1;" : "=r"(hb) : "f"(x));
    float hf = __uint_as_float(hb);
    float l = x - hf;
    unsigned lb;
    asm("cvt.rna.tf32.f32 %0, %1;" : "=r"(lb) : "f"(l));
    hi = hf;
    lo = __uint_as_float(lb);
}

#define MMA_TF32(c, a, b)                                                     \
    asm volatile(                                                             \
        "mma.sync.aligned.m16n8k8.row.col.f32.tf32.tf32.f32 "                 \
        "{%0,%1,%2,%3}, {%4,%5,%6,%7}, {%8,%9}, {%0,%1,%2,%3};"               \
        : "+f"((c)[0]), "+f"((c)[1]), "+f"((c)[2]), "+f"((c)[3])              \
        : "r"((a)[0]), "r"((a)[1]), "r"((a)[2]), "r"((a)[3]),                 \
          "r"((b)[0]), "r"((b)[1]))

#define MMA_F16(c, a, b)                                                      \
    asm volatile(                                                             \
        "mma.sync.aligned.m16n8k16.row.col.f32.f16.f16.f32 "                  \
        "{%0,%1,%2,%3}, {%4,%5,%6,%7}, {%8,%9}, {%0,%1,%2,%3};"               \
        : "+f"((c)[0]), "+f"((c)[1]), "+f"((c)[2]), "+f"((c)[3])              \
        : "r"((a)[0]), "r"((a)[1]), "r"((a)[2]), "r"((a)[3]),                 \
          "r"((b)[0]), "r"((b)[1]))

__device__ __forceinline__ void cp16(uint32_t dst, const void* src) {
    asm volatile("cp.async.cg.shared.global [%0], [%1], 16;" :: "r"(dst), "l"(src));
}
#define CP_COMMIT() asm volatile("cp.async.commit_group;")
#define CP_WAIT1()  asm volatile("cp.async.wait_group 1;")
#define CP_WAIT0()  asm volatile("cp.async.wait_group 0;")

// gemm stage layout: 4 planes x 128 rows x 20 floats
#define PLANE 2560
#define STAGE 10240

// scan smem layout (halves): W stride 136, H stride 136
#define SW_H 0
#define SW_L 17408
#define SH_H 34816
#define SH_L 39168
#define SC_HALVES 43520

// ------------------ split kernels ------------------
__global__ __launch_bounds__(256) void k_split(const float* __restrict__ s,
                                               float* __restrict__ dh,
                                               float* __restrict__ dl, int n4) {
    int i = blockIdx.x * 256 + threadIdx.x;
    if (i < n4) {
        float4 v = ((const float4*)s)[i];
        float4 h4, l4;
        tf32split(v.x, h4.x, l4.x);
        tf32split(v.y, h4.y, l4.y);
        tf32split(v.z, h4.z, l4.z);
        tf32split(v.w, h4.w, l4.w);
        ((float4*)dh)[i] = h4;
        ((float4*)dl)[i] = l4;
    }
}

__global__ __launch_bounds__(256) void k_split16(const float* __restrict__ s,
                                                 __half* __restrict__ dh,
                                                 __half* __restrict__ dl, int n) {
    int i = blockIdx.x * 256 + threadIdx.x;
    if (i < n) {
        float v = s[i];
        __half h = __float2half_rn(v);
        float r = v - __half2float(h);
        dh[i] = h;
        dl[i] = __float2half_rn(r * 4096.0f);
    }
}

// ------------------ embedding ------------------
__global__ __launch_bounds__(256) void k_embed(const int* __restrict__ w,
                                               const float* __restrict__ emb) {
    int i = blockIdx.x * 256 + threadIdx.x;
    float v = emb[(size_t)w[i >> 7] * NE + (i & 127)];
    float h, l;
    tf32split(v, h, l);
    g_ah[i] = h;
    g_al[i] = l;
}

// ------------------ zero h planes + barrier counters + mask transpose -----
__global__ __launch_bounds__(256) void k_zero(const float* __restrict__ mask) {
    int i = blockIdx.x * 256 + threadIdx.x;
    if (i < 2 * NB * NH) {
        g_hph16[i] = __float2half_rn(0.0f);
        g_hpl16[i] = __float2half_rn(0.0f);
    }
    if (i < NL * NB) {
        int t = i >> 5, b = i & 31;
        g_maskt[i] = mask[b * NL + t];
    }
    if (i < 2) g_barcnt2[i] = 0u;
}

// ------------------ 3xTF32 legacy-mma GEMM (gx layers + dec1) ------------
// gxt=1: write C transposed as [t][n][b] (per dir), b = m>>7, t = m&127.
__global__ __launch_bounds__(256) void k_gemm2(const float* __restrict__ Ahp,
                                               const float* __restrict__ Alp,
                                               const float* __restrict__ Whp,
                                               const float* __restrict__ Wlp,
                                               const float* __restrict__ bias,
                                               float* __restrict__ C,
                                               int K, int N,
                                               long long wStr, long long bStr,
                                               long long cStr, int mode, int gxt) {
    extern __shared__ float smf[];
    uint32_t smb = (uint32_t)__cvta_generic_to_shared(smf);

    int d = blockIdx.z;
    Whp += (size_t)d * wStr;
    Wlp += (size_t)d * wStr;
    bias += (size_t)d * bStr;
    C += (size_t)d * cStr;

    int tid = threadIdx.x;
    int m0 = blockIdx.y << 7, n0 = blockIdx.x << 7;
    int lr = tid >> 2, lkq = (tid & 3) << 2;

    const float* pA0h = Ahp + (size_t)(m0 + lr) * K + lkq;
    const float* pA1h = Ahp + (size_t)(m0 + lr + 64) * K + lkq;
    const float* pA0l = Alp + (size_t)(m0 + lr) * K + lkq;
    const float* pA1l = Alp + (size_t)(m0 + lr + 64) * K + lkq;
    const float* pB0h = Whp + (size_t)(n0 + lr) * K + lkq;
    const float* pB1h = Whp + (size_t)(n0 + lr + 64) * K + lkq;
    const float* pB0l = Wlp + (size_t)(n0 + lr) * K + lkq;
    const float* pB1l = Wlp + (size_t)(n0 + lr + 64) * K + lkq;

    uint32_t o0 = (uint32_t)((0 * PLANE + lr * 20 + lkq) * 4);
    uint32_t o1 = (uint32_t)((0 * PLANE + (lr + 64) * 20 + lkq) * 4);
    uint32_t o2 = (uint32_t)((1 * PLANE + lr * 20 + lkq) * 4);
    uint32_t o3 = (uint32_t)((1 * PLANE + (lr + 64) * 20 + lkq) * 4);
    uint32_t o4 = (uint32_t)((2 * PLANE + lr * 20 + lkq) * 4);
    uint32_t o5 = (uint32_t)((2 * PLANE + (lr + 64) * 20 + lkq) * 4);
    uint32_t o6 = (uint32_t)((3 * PLANE + lr * 20 + lkq) * 4);
    uint32_t o7 = (uint32_t)((3 * PLANE + (lr + 64) * 20 + lkq) * 4);

    int wid = tid >> 5, lane = tid & 31;
    int gid = lane >> 2, t4 = lane & 3;
    int wm = (wid >> 2) << 6;
    int wn = (wid & 3) << 5;

    float acc[4][4][4];
#pragma unroll
    for (int mt = 0; mt < 4; mt++)
#pragma unroll
        for (int nt = 0; nt < 4; nt++)
#pragma unroll
            for (int r = 0; r < 4; r++) acc[mt][nt][r] = 0.0f;

    int T = K >> 4;
    {
        uint32_t b = smb;
        cp16(b + o0, pA0h); cp16(b + o1, pA1h);
        cp16(b + o2, pA0l); cp16(b + o3, pA1l);
        cp16(b + o4, pB0h); cp16(b + o5, pB1h);
        cp16(b + o6, pB0l); cp16(b + o7, pB1l);
        CP_COMMIT();
    }

    for (int kt = 0; kt < T; kt++) {
        int s = kt & 1;
        if (kt + 1 < T) {
            int ko = (kt + 1) << 4;
            uint32_t b = smb + (uint32_t)((s ^ 1) * STAGE * 4);
            cp16(b + o0, pA0h + ko); cp16(b + o1, pA1h + ko);
            cp16(b + o2, pA0l + ko); cp16(b + o3, pA1l + ko);
            cp16(b + o4, pB0h + ko); cp16(b + o5, pB1h + ko);
            cp16(b + o6, pB0l + ko); cp16(b + o7, pB1l + ko);
            CP_COMMIT();
            CP_WAIT1();
        } else {
            CP_WAIT0();
        }
        __syncthreads();
        const float* S = smf + s * STAGE;

#pragma unroll
        for (int k8 = 0; k8 < 16; k8 += 8) {
            unsigned ah[4][4], al[4][4];
#pragma unroll
            for (int mt = 0; mt < 4; mt++) {
                int r0i = (wm + (mt << 4) + gid) * 20 + k8 + t4;
                int r1i = (wm + (mt << 4) + gid + 8) * 20 + k8 + t4;
                ah[mt][0] = __float_as_uint(S[r0i]);
                ah[mt][1] = __float_as_uint(S[r1i]);
                ah[mt][2] = __float_as_uint(S[r0i + 4]);
                ah[mt][3] = __float_as_uint(S[r1i + 4]);
                al[mt][0] = __float_as_uint(S[PLANE + r0i]);
                al[mt][1] = __float_as_uint(S[PLANE + r1i]);
                al[mt][2] = __float_as_uint(S[PLANE + r0i + 4]);
                al[mt][3] = __float_as_uint(S[PLANE + r1i + 4]);
            }
            unsigned bh[4][2], bl[4][2];
#pragma unroll
            for (int nt = 0; nt < 4; nt++) {
                int ci = (wn + (nt << 3) + gid) * 20 + k8 + t4;
                bh[nt][0] = __float_as_uint(S[2 * PLANE + ci]);
                bh[nt][1] = __float_as_uint(S[2 * PLANE + ci + 4]);
                bl[nt][0] = __float_as_uint(S[3 * PLANE + ci]);
                bl[nt][1] = __float_as_uint(S[3 * PLANE + ci + 4]);
            }
#pragma unroll
            for (int mt = 0; mt < 4; mt++)
#pragma unroll
                for (int nt = 0; nt < 4; nt++) {
                    MMA_TF32(acc[mt][nt], ah[mt], bh[nt]);
                    MMA_TF32(acc[mt][nt], ah[mt], bl[nt]);
                    MMA_TF32(acc[mt][nt], al[mt], bh[nt]);
                }
        }
        __syncthreads();
    }

#pragma unroll
    for (int mt = 0; mt < 4; mt++) {
#pragma unroll
        for (int nt = 0; nt < 4; nt++) {
            int m = m0 + wm + (mt << 4) + gid;
            int n = n0 + wn + (nt << 3) + (t4 << 1);
            float bv0 = bias[n], bv1 = bias[n + 1];
            float v0 = acc[mt][nt][0] + bv0;
            float v1 = acc[mt][nt][1] + bv1;
            float v2 = acc[mt][nt][2] + bv0;
            float v3 = acc[mt][nt][3] + bv1;
            if (mode) {
                v0 = fmaxf(v0, 0.0f); v1 = fmaxf(v1, 0.0f);
                v2 = fmaxf(v2, 0.0f); v3 = fmaxf(v3, 0.0f);
            }
            if (gxt) {
                int b = m >> 7;
                int tt = m & 127;
                C[((size_t)tt * NG + n) * NB + b] = v0;
                C[((size_t)tt * NG + n + 1) * NB + b] = v1;
                C[((size_t)(tt + 8) * NG + n) * NB + b] = v2;
                C[((size_t)(tt + 8) * NG + n + 1) * NB + b] = v3;
            } else {
                float2 p0 = {v0, v1};
                float2 p1 = {v2, v3};
                *(float2*)(C + (size_t)m * N + n) = p0;
                *(float2*)(C + (size_t)(m + 8) * N + n) = p1;
                if (mode == 2) {
                    float h, l;
                    size_t i0 = (size_t)m * N + n;
                    size_t i1 = (size_t)(m + 8) * N + n;
                    tf32split(v0, h, l); g_hidh[i0] = h;     g_hidl[i0] = l;
                    tf32split(v1, h, l); g_hidh[i0 + 1] = h; g_hidl[i0 + 1] = l;
                    tf32split(v2, h, l); g_hidh[i1] = h;     g_hidl[i1] = l;
                    tf32split(v3, h, l); g_hidh[i1 + 1] = h; g_hidl[i1 + 1] = l;
                }
            }
        }
    }
}

// ------------------ decoder2 mma: logits tile + online softmax partials ----
__global__ __launch_bounds__(256) void k_dec2m(const float* __restrict__ b2) {
    extern __shared__ float smf[];
    uint32_t smb = (uint32_t)__cvta_generic_to_shared(smf);
    __shared__ float wmax[256];
    __shared__ int   warg[256];
    __shared__ float wsum[256];
    __shared__ float bmx[128];

    const float* Ahp = g_wh + OFF_W2;
    const float* Alp = g_wl + OFF_W2;

    int tid = threadIdx.x;
    int vt = blockIdx.x;
    int v0 = vt << 7;
    int n0 = blockIdx.y << 7;
    int lr = tid >> 2, lkq = (tid & 3) << 2;
    const int K = 128;

    const float* pA0h = Ahp + (size_t)(v0 + lr) * K + lkq;
    const float* pA1h = Ahp + (size_t)(v0 + lr + 64) * K + lkq;
    const float* pA0l = Alp + (size_t)(v0 + lr) * K + lkq;
    const float* pA1l = Alp + (size_t)(v0 + lr + 64) * K + lkq;
    const float* pB0h = g_hidh + (size_t)(n0 + lr) * K + lkq;
    const float* pB1h = g_hidh + (size_t)(n0 + lr + 64) * K + lkq;
    const float* pB0l = g_hidl + (size_t)(n0 + lr) * K + lkq;
    const float* pB1l = g_hidl + (size_t)(n0 + lr + 64) * K + lkq;

    uint32_t o0 = (uint32_t)((0 * PLANE + lr * 20 + lkq) * 4);
    uint32_t o1 = (uint32_t)((0 * PLANE + (lr + 64) * 20 + lkq) * 4);
    uint32_t o2 = (uint32_t)((1 * PLANE + lr * 20 + lkq) * 4);
    uint32_t o3 = (uint32_t)((1 * PLANE + (lr + 64) * 20 + lkq) * 4);
    uint32_t o4 = (uint32_t)((2 * PLANE + lr * 20 + lkq) * 4);
    uint32_t o5 = (uint32_t)((2 * PLANE + (lr + 64) * 20 + lkq) * 4);
    uint32_t o6 = (uint32_t)((3 * PLANE + lr * 20 + lkq) * 4);
    uint32_t o7 = (uint32_t)((3 * PLANE + (lr + 64) * 20 + lkq) * 4);

    int wid = tid >> 5, lane = tid & 31;
    int gid = lane >> 2, t4 = lane & 3;
    int wm = (wid >> 2) << 6;
    int wn = (wid & 3) << 5;

    float acc[4][4][4];
#pragma unroll
    for (int mt = 0; mt < 4; mt++)
#pragma unroll
        for (int nt = 0; nt < 4; nt++)
#pragma unroll
            for (int r = 0; r < 4; r++) acc[mt][nt][r] = 0.0f;

    const int T = 8;
    {
        uint32_t b = smb;
        cp16(b + o0, pA0h); cp16(b + o1, pA1h);
        cp16(b + o2, pA0l); cp16(b + o3, pA1l);
        cp16(b + o4, pB0h); cp16(b + o5, pB1h);
        cp16(b + o6, pB0l); cp16(b + o7, pB1l);
        CP_COMMIT();
    }
    for (int kt = 0; kt < T; kt++) {
        int s = kt & 1;
        if (kt + 1 < T) {
            int ko = (kt + 1) << 4;
            uint32_t b = smb + (uint32_t)((s ^ 1) * STAGE * 4);
            cp16(b + o0, pA0h + ko); cp16(b + o1, pA1h + ko);
            cp16(b + o2, pA0l + ko); cp16(b + o3, pA1l + ko);
            cp16(b + o4, pB0h + ko); cp16(b + o5, pB1h + ko);
            cp16(b + o6, pB0l + ko); cp16(b + o7, pB1l + ko);
            CP_COMMIT();
            CP_WAIT1();
        } else {
            CP_WAIT0();
        }
        __syncthreads();
        const float* S = smf + s * STAGE;
#pragma unroll
        for (int k8 = 0; k8 < 16; k8 += 8) {
            unsigned ah[4][4], al[4][4];
#pragma unroll
            for (int mt = 0; mt < 4; mt++) {
                int r0i = (wm + (mt << 4) + gid) * 20 + k8 + t4;
                int r1i = (wm + (mt << 4) + gid + 8) * 20 + k8 + t4;
                ah[mt][0] = __float_as_uint(S[r0i]);
                ah[mt][1] = __float_as_uint(S[r1i]);
                ah[mt][2] = __float_as_uint(S[r0i + 4]);
                ah[mt][3] = __float_as_uint(S[r1i + 4]);
                al[mt][0] = __float_as_uint(S[PLANE + r0i]);
                al[mt][1] = __float_as_uint(S[PLANE + r1i]);
                al[mt][2] = __float_as_uint(S[PLANE + r0i + 4]);
                al[mt][3] = __float_as_uint(S[PLANE + r1i + 4]);
            }
            unsigned bh[4][2], bl[4][2];
#pragma unroll
            for (int nt = 0; nt < 4; nt++) {
                int ci = (wn + (nt << 3) + gid) * 20 + k8 + t4;
                bh[nt][0] = __float_as_uint(S[2 * PLANE + ci]);
                bh[nt][1] = __float_as_uint(S[2 * PLANE + ci + 4]);
                bl[nt][0] = __float_as_uint(S[3 * PLANE + ci]);
                bl[nt][1] = __float_as_uint(S[3 * PLANE + ci + 4]);
            }
#pragma unroll
            for (int mt = 0; mt < 4; mt++)
#pragma unroll
                for (int nt = 0; nt < 4; nt++) {
                    MMA_TF32(acc[mt][nt], ah[mt], bh[nt]);
                    MMA_TF32(acc[mt][nt], ah[mt], bl[nt]);
                    MMA_TF32(acc[mt][nt], al[mt], bh[nt]);
                }
        }
        __syncthreads();
    }

    float bvv[4][2];
#pragma unroll
    for (int mt = 0; mt < 4; mt++) {
        bvv[mt][0] = b2[v0 + wm + (mt << 4) + gid];
        bvv[mt][1] = b2[v0 + wm + (mt << 4) + gid + 8];
    }
#pragma unroll
    for (int mt = 0; mt < 4; mt++)
#pragma unroll
        for (int nt = 0; nt < 4; nt++) {
            acc[mt][nt][0] += bvv[mt][0];
            acc[mt][nt][1] += bvv[mt][0];
            acc[mt][nt][2] += bvv[mt][1];
            acc[mt][nt][3] += bvv[mt][1];
        }

#pragma unroll
    for (int nt = 0; nt < 4; nt++) {
#pragma unroll
        for (int c = 0; c < 2; c++) {
            float lm = -1e30f;
            int la = 0;
#pragma unroll
            for (int mt = 0; mt < 4; mt++)
#pragma unroll
                for (int ro = 0; ro < 2; ro++) {
                    float lg = acc[mt][nt][ro * 2 + c];
                    if (lg > lm) {
                        lm = lg;
                        la = v0 + wm + (mt << 4) + gid + ro * 8;
                    }
                }
#pragma unroll
            for (int off = 4; off <= 16; off <<= 1) {
                float om = __shfl_xor_sync(0xffffffffu, lm, off);
                int oa = __shfl_xor_sync(0xffffffffu, la, off);
                if (om > lm || (om == lm && oa < la)) { lm = om; la = oa; }
            }
            if (gid == 0) {
                int tcol = wn + (nt << 3) + (t4 << 1) + c;
                wmax[(wm >> 6) * 128 + tcol] = lm;
                warg[(wm >> 6) * 128 + tcol] = la;
            }
        }
    }
    __syncthreads();
    float fm = 0.0f;
    int fa = 0;
    if (tid < 128) {
        float ma = wmax[tid], mb = wmax[128 + tid];
        if (mb > ma) { fm = mb; fa = warg[128 + tid]; }
        else { fm = ma; fa = warg[tid]; }
        bmx[tid] = fm;
    }
    __syncthreads();

#pragma unroll
    for (int nt = 0; nt < 4; nt++) {
#pragma unroll
        for (int c = 0; c < 2; c++) {
            int tcol = wn + (nt << 3) + (t4 << 1) + c;
            float mx = bmx[tcol];
            float s = 0.0f;
#pragma unroll
            for (int mt = 0; mt < 4; mt++)
#pragma unroll
                for (int ro = 0; ro < 2; ro++)
                    s += __expf(acc[mt][nt][ro * 2 + c] - mx);
#pragma unroll
            for (int off = 4; off <= 16; off <<= 1)
                s += __shfl_xor_sync(0xffffffffu, s, off);
            if (gid == 0) wsum[(wm >> 6) * 128 + tcol] = s;
        }
    }
    __syncthreads();
    if (tid < 128) {
        size_t tok = (size_t)(n0 + tid);
        g_pmax[tok * NVT + vt] = fm;
        g_parg[tok * NVT + vt] = fa;
        g_psum[tok * NVT + vt] = wsum[tid] + wsum[128 + tid];
    }
}

// ------------------ persistent BiLSTM scan v5: fp16 hi/lo mma --------------
// Same v4 topology (proven). Whh + h in fp16 hi / scaled-lo planes,
// mma.m16n8k16.f16 with dual fp32 accumulators: result = acc1 + acc2/4096.
__global__ __launch_bounds__(256) void k_scan4(const float* __restrict__ gx,
                                               const __half* __restrict__ whh_h16,
                                               const __half* __restrict__ whh_l16) {
    extern __shared__ __half smh[];
    uint32_t smb = (uint32_t)__cvta_generic_to_shared(smh);

    int tid = threadIdx.x;
    int bid = blockIdx.x;
    int d = bid >> 6;
    int ks = (bid >> 4) & 3;
    int gt = bid & 15;
    int g0 = gt << 7;
    int k0 = ks << 7;

    // preload Whh fp16 hi/lo tiles (once per layer): 128 rows x 128 halves each
#pragma unroll
    for (int j = 0; j < 16; j++) {
        int idx = tid + (j << 8);
        int p = idx >> 11;
        int rem = idx & 2047;
        int row = rem >> 4;
        int seg = rem & 15;
        const __half* src = (p ? whh_l16 : whh_h16) +
                            (size_t)(d * NG + g0 + row) * NH + k0 + (seg << 3);
        uint4 v = __ldg((const uint4*)src);
        *(uint4*)&smh[(p ? SW_L : SW_H) + row * 136 + (seg << 3)] = v;
    }

    int wid = tid >> 5, lane = tid & 31;
    int gid = lane >> 2, t4 = lane & 3;
    int rowbase = wid << 4;

    // combine role
    int jt = bid & 63;
    int cb = tid & 31;
    int jl = tid >> 5;
    int cj = (jt << 3) + jl;
    float creg = 0.0f, hreg = 0.0f;

    const float* gxd = gx + (size_t)d * NL * NG * NB;

    __syncthreads();

    for (int s = 0; s < NL; s++) {
        int t = d ? (NL - 1 - s) : s;

        // prefetch gx + mask (coalesced, independent of partials)
        float gin[4];
        {
            const float* gxr = gxd + (size_t)t * NG * NB + cb;
#pragma unroll
            for (int gi = 0; gi < 4; gi++)
                gin[gi] = __ldg(&gxr[(size_t)(gi * NH + cj) * NB]);
        }
        float mt = g_maskt[t * NB + cb];

        // stage h fp16 planes via cp.async (32 rows x 128 halves x 2 planes)
        {
#pragma unroll
            for (int j = 0; j < 4; j++) {
                int idx = tid + (j << 8);
                int p = idx >> 9;
                int rem = idx & 511;
                int row = rem >> 4;
                int seg = rem & 15;
                const __half* src = (p ? g_hpl16 : g_hph16) +
                                    (size_t)(d * NB + row) * NH + k0 + (seg << 3);
                uint32_t dst = smb + (uint32_t)(((p ? SH_L : SH_H) + row * 136 + (seg << 3)) << 1);
                cp16(dst, src);
            }
            CP_COMMIT();
            CP_WAIT0();
        }
        __syncthreads();

        // mma partial: [128 gates] x [32 b] over k-slice 128 (k16 steps)
        float acc1[4][4], acc2[4][4];
#pragma unroll
        for (int nt = 0; nt < 4; nt++)
#pragma unroll
            for (int r = 0; r < 4; r++) { acc1[nt][r] = 0.0f; acc2[nt][r] = 0.0f; }

#pragma unroll
        for (int kk = 0; kk < 8; kk++) {
            int kb = (kk << 4) + (t4 << 1);
            const __half* wr = &smh[SW_H + (rowbase + gid) * 136 + kb];
            const __half* wl = &smh[SW_L + (rowbase + gid) * 136 + kb];
            unsigned ah[4], al[4];
            ah[0] = *(const unsigned*)wr;
            ah[1] = *(const unsigned*)(wr + 8 * 136);
            ah[2] = *(const unsigned*)(wr + 8);
            ah[3] = *(const unsigned*)(wr + 8 * 136 + 8);
            al[0] = *(const unsigned*)wl;
            al[1] = *(const unsigned*)(wl + 8 * 136);
            al[2] = *(const unsigned*)(wl + 8);
            al[3] = *(const unsigned*)(wl + 8 * 136 + 8);
#pragma unroll
            for (int nt = 0; nt < 4; nt++) {
                const __half* hr = &smh[SH_H + ((nt << 3) + gid) * 136 + kb];
                const __half* hl = &smh[SH_L + ((nt << 3) + gid) * 136 + kb];
                unsigned bh[2], bl[2];
                bh[0] = *(const unsigned*)hr;
                bh[1] = *(const unsigned*)(hr + 8);
                bl[0] = *(const unsigned*)hl;
                bl[1] = *(const unsigned*)(hl + 8);
                MMA_F16(acc1[nt], ah, bh);
                MMA_F16(acc2[nt], ah, bl);
                MMA_F16(acc2[nt], al, bh);
            }
        }

        // store partials (combine hi + lo/4096)
        {
            size_t pbase = ((size_t)(d * 4 + ks) * NG + g0) * NB;
            int grow = rowbase + gid;
            const float sc = 1.0f / 4096.0f;
#pragma unroll
            for (int nt = 0; nt < 4; nt++) {
                int b = (nt << 3) + (t4 << 1);
                float2 p0 = {acc1[nt][0] + acc2[nt][0] * sc,
                             acc1[nt][1] + acc2[nt][1] * sc};
                float2 p1 = {acc1[nt][2] + acc2[nt][2] * sc,
                             acc1[nt][3] + acc2[nt][3] * sc};
                *(float2*)&g_part[pbase + (size_t)grow * NB + b] = p0;
                *(float2*)&g_part[pbase + (size_t)(grow + 8) * NB + b] = p1;
            }
        }
        gridbar_d(d);

        // combine: one (b, j) per thread
        {
            float gate[4];
#pragma unroll
            for (int gi = 0; gi < 4; gi++) {
                int g = gi * NH + cj;
                float v = gin[gi];
#pragma unroll
                for (int kss = 0; kss < 4; kss++)
                    v += __ldcg(&g_part[((size_t)(d * 4 + kss) * NG + g) * NB + cb]);
                gate[gi] = v;
            }
            float cn = sigf(gate[1]) * creg + sigf(gate[0]) * tanhf_fast(gate[2]);
            float hn = sigf(gate[3]) * tanhf_fast(cn);
            hreg = hreg + (hn - hreg) * mt;
            creg = creg + (cn - creg) * mt;
            // fp16 hi / scaled-lo state planes
            __half hh16 = __float2half_rn(hreg);
            float rem = hreg - __half2float(hh16);
            __half hl16 = __float2half_rn(rem * 4096.0f);
            size_t hidx = (size_t)(d * NB + cb) * NH + cj;
            g_hph16[hidx] = hh16;
            g_hpl16[hidx] = hl16;
            // tf32 split sequence output (next layer's A planes)
            float ah_, al_;
            tf32split(hreg, ah_, al_);
            size_t oidx = ((size_t)cb * NL + t) * 1024 + (d << 9) + cj;
            g_ah[oidx] = ah_;
            g_al[oidx] = al_;
        }
        gridbar_d(d);
    }
}

// ------------------ per-token combine ------------------
__global__ __launch_bounds__(256) void k_comb(const float* __restrict__ w2,
                                              const float* __restrict__ b2,
                                              const int* __restrict__ tgt,
                                              const float* __restrict__ cew,
                                              float* __restrict__ dout) {
    int warp = threadIdx.x >> 5, lane = threadIdx.x & 31;
    int m = blockIdx.x * 8 + warp;

    float lm = -1e30f, ls = 0.0f;
    int la = 0;
    for (int vt = lane; vt < NVT; vt += 32) {
        float tmx = g_pmax[(size_t)m * NVT + vt];
        float tsm = g_psum[(size_t)m * NVT + vt];
        int tag = g_parg[(size_t)m * NVT + vt];
        if (tmx > lm) {
            ls = ls * __expf(lm - tmx) + tsm;
            lm = tmx;
            la = tag;
        } else {
            ls += tsm * __expf(tmx - lm);
        }
    }
#pragma unroll
    for (int off = 16; off; off >>= 1) {
        float om = __shfl_down_sync(0xffffffffu, lm, off);
        float os = __shfl_down_sync(0xffffffffu, ls, off);
        int oa = __shfl_down_sync(0xffffffffu, la, off);
        float nm = fmaxf(lm, om);
        float ns = ls * __expf(lm - nm) + os * __expf(om - nm);
        int na = (om > lm) ? oa : ((om == lm && oa < la) ? oa : la);
        lm = nm; ls = ns; la = na;
    }

    int tg = tgt[m];
    float4 hv = *(const float4*)&g_hid[(size_t)m * 128 + lane * 4];
    float4 wv = *(const float4*)&w2[(size_t)tg * 128 + lane * 4];
    float dp = hv.x * wv.x + hv.y * wv.y + hv.z * wv.z + hv.w * wv.w;
#pragma unroll
    for (int off = 16; off; off >>= 1) dp += __shfl_down_sync(0xffffffffu, dp, off);

    if (lane == 0) {
        float logit_t = dp + b2[tg];
        float lse = lm + logf(ls);
        float nll = lse - logit_t;
        float w = cew[tg];
        g_nllw[m] = nll * w;
        g_wtok[m] = w;
        dout[1 + m] = (float)la;
    }
}

// ------------------ final loss reduce ------------------
__global__ __launch_bounds__(256) void k_loss(float* __restrict__ dout) {
    __shared__ float s1[256];
    __shared__ float s2[256];
    int tid = threadIdx.x;
    float a = 0.0f, b = 0.0f;
    for (int i = tid; i < NTOK; i += 256) { a += g_nllw[i]; b += g_wtok[i]; }
    s1[tid] = a; s2[tid] = b;
    __syncthreads();
    for (int off = 128; off; off >>= 1) {
        if (tid < off) { s1[tid] += s1[tid + off]; s2[tid] += s2[tid + off]; }
        __syncthreads();
    }
    if (tid == 0) dout[0] = s1[0] / s2[0];
}

// ------------------ launch ------------------
extern "C" void kernel_launch(void* const* d_in, const int* in_sizes, int n_in,
                              void* d_out, int out_size) {
    const int* inp_word = (const int*)d_in[0];
    const float* inp_mask = (const float*)d_in[1];
    const int* tgt_word = (const int*)d_in[3];
    const float* emb = (const float*)d_in[4];
    const float* w_ih0 = (const float*)d_in[5];
    const float* w_hh0 = (const float*)d_in[6];
    const float* b0 = (const float*)d_in[7];
    const float* w_ih = (const float*)d_in[8];
    const float* w_hh = (const float*)d_in[9];
    const float* bb = (const float*)d_in[10];
    const float* dec_w1 = (const float*)d_in[11];
    const float* dec_b1 = (const float*)d_in[12];
    const float* dec_w2 = (const float*)d_in[13];
    const float* dec_b2 = (const float*)d_in[14];
    const float* cew = (const float*)d_in[15];
    float* out = (float*)d_out;

    float *pgx, *phid, *pwh, *pwl, *pah, *pal;
    __half *pw16h, *pw16l;
    cudaGetSymbolAddress((void**)&pgx, g_gx);
    cudaGetSymbolAddress((void**)&phid, g_hid);
    cudaGetSymbolAddress((void**)&pwh, g_wh);
    cudaGetSymbolAddress((void**)&pwl, g_wl);
    cudaGetSymbolAddress((void**)&pah, g_ah);
    cudaGetSymbolAddress((void**)&pal, g_al);
    cudaGetSymbolAddress((void**)&pw16h, g_whh16h);
    cudaGetSymbolAddress((void**)&pw16l, g_whh16l);

    const int gsm = 2 * STAGE * 4;        // 81920 bytes
    const int ssm = SC_HALVES * 2;        // 87040 bytes
    cudaFuncSetAttribute(k_gemm2, cudaFuncAttributeMaxDynamicSharedMemorySize, gsm);
    cudaFuncSetAttribute(k_dec2m, cudaFuncAttributeMaxDynamicSharedMemorySize, gsm);
    cudaFuncSetAttribute(k_scan4, cudaFuncAttributeMaxDynamicSharedMemorySize, ssm);

    // launch order arranged so ncu (-s 5 -c 1) captures k_scan4 (index 5)
    k_split<<<512, 256>>>(w_ih0, pwh + OFF_WIH0, pwl + OFF_WIH0, 524288 / 4);     // 0
    k_embed<<<(NTOK * NE) / 256, 256>>>(inp_word, emb);                           // 1
    k_gemm2<<<dim3(NG / 128, NTOK / 128, 2), 256, gsm>>>(                         // 2
        pah, pal, pwh + OFF_WIH0, pwl + OFF_WIH0, b0, pgx,
        NE, NG, (long long)NG * NE, NG, (long long)NL * NG * NB, 0, 1);
    k_split16<<<8192, 256>>>(w_hh0, pw16h, pw16l, 2 * NG * NH);                   // 3
    k_zero<<<128, 256>>>(inp_mask);                                               // 4
    k_scan4<<<128, 256, ssm>>>(pgx, pw16h, pw16l);                                // 5 <- profiled

    // remaining weight splits
    k_split<<<8192, 256>>>(w_ih, pwh + OFF_WIH1, pwl + OFF_WIH1, 8388608 / 4);
    k_split<<<128, 256>>>(dec_w1, pwh + OFF_W1, pwl + OFF_W1, 131072 / 4);
    k_split<<<4000, 256>>>(dec_w2, pwh + OFF_W2, pwl + OFF_W2, 4096000 / 4);
    k_split16<<<16384, 256>>>(w_hh, pw16h + 2 * NG * NH, pw16l + 2 * NG * NH,
                              4 * NG * NH);

    // layer 1
    k_gemm2<<<dim3(NG / 128, NTOK / 128, 2), 256, gsm>>>(
        pah, pal, pwh + OFF_WIH1, pwl + OFF_WIH1, bb, pgx,
        1024, NG, (long long)NG * 1024, NG, (long long)NL * NG * NB, 0, 1);
    k_zero<<<128, 256>>>(inp_mask);
    k_scan4<<<128, 256, ssm>>>(pgx, pw16h + 2 * NG * NH, pw16l + 2 * NG * NH);

    // layer 2
    k_gemm2<<<dim3(NG / 128, NTOK / 128, 2), 256, gsm>>>(
        pah, pal, pwh + OFF_WIH1 + 4194304, pwl + OFF_WIH1 + 4194304,
        bb + 2 * NG, pgx,
        1024, NG, (long long)NG * 1024, NG, (long long)NL * NG * NB, 0, 1);
    k_zero<<<128, 256>>>(inp_mask);
    k_scan4<<<128, 256, ssm>>>(pgx, pw16h + 4 * NG * NH, pw16l + 4 * NG * NH);

    // decoder layer 1 (relu, writes g_hid + split planes)
    k_gemm2<<<dim3(1, NTOK / 128, 1), 256, gsm>>>(
        pah, pal, pwh + OFF_W1, pwl + OFF_W1, dec_b1, phid,
        1024, 128, 0, 0, 0, 2, 0);

    // decoder layer 2 + fused online softmax partials
    k_dec2m<<<dim3(NVT, NTOK / 128), 256, gsm>>>(dec_b2);

    // per-token combine
    k_comb<<<NTOK / 8, 256>>>(dec_w2, dec_b2, tgt_word, cew, out);

    // loss reduce
    k_loss<<<1, 256>>>(out);
}